// round 11
// baseline (speedup 1.0000x reference)
#include <cuda_runtime.h>
#include <math.h>

#define BATCH 8
#define CH    64
#define HH    256
#define WW    512
#define KF    64      // W_FREQ low bins kept

// ---------------- device globals (scratch; no allocation allowed) -------------
__device__ float2 g_tw512[512];                       // e^{-2*pi*i*r/512}
__device__ float2 g_filtm1[BATCH * KF * HH];          // (filt-1), layout [b][k][h]
__device__ float  g_pooled[BATCH * CH * HH * KF];     // [b][c][h][wf]

// ---------------- tiny helpers -------------------------------------------------
__device__ __forceinline__ float2 cmulf2(float2 a, float2 b) {
    return make_float2(a.x * b.x - a.y * b.y, a.x * b.y + a.y * b.x);
}

// ---------------- twiddle init (runs every launch; deterministic, ~1us) --------
__global__ void k_tw() {
    int i = threadIdx.x;
    if (i < 512) {
        float s, c;
        sincospif((float)i / 256.0f, &s, &c);   // angle = pi * i/256 = 2*pi*i/512
        g_tw512[i] = make_float2(c, -s);
    }
}

// ---------------- pooled means: x.reshape(B,C,H,64,8).mean(-1) -----------------
__global__ void k_pool(const float* __restrict__ x) {
    int idx = blockIdx.x * blockDim.x + threadIdx.x;   // one output per thread
    if (idx >= BATCH * CH * HH * KF) return;
    const float4* x4 = (const float4*)x;
    float4 a = x4[idx * 2];
    float4 b = x4[idx * 2 + 1];
    g_pooled[idx] = (a.x + a.y + a.z + a.w + b.x + b.y + b.z + b.w) * 0.125f;
}

// ---------------- filt-1 per (b, h): 64x64x64 matmul + nonlinearity ------------
// grid = B*H blocks of 64 threads (thread = wf)
__global__ void k_filt(const float* __restrict__ conv_w,
                       const float* __restrict__ conv_b,
                       const float* __restrict__ dt) {
    __shared__ float P[64 * 64];    // pooled[c][wf]
    __shared__ float Wm[64 * 64];   // conv_w[o][c]
    __shared__ float bs[64];
    int b = blockIdx.x >> 8;
    int h = blockIdx.x & 255;
    int t = threadIdx.x;            // 0..63

    for (int i = t; i < 4096; i += 64) Wm[i] = conv_w[i];
    bs[t] = conv_b[t];
    for (int c = 0; c < 64; c++)
        P[c * 64 + t] = g_pooled[((b * 64 + c) * 256 + h) * 64 + t];
    __syncthreads();

    float dtb = dt[b];
    float fre = 0.f, fim = 0.f;
    const float PIF = 3.14159265358979323846f;
    for (int r = 0; r < 32; r++) {
        float p1 = bs[r], p2 = bs[r + 32];
        const float* w1 = &Wm[r * 64];
        const float* w2 = &Wm[(r + 32) * 64];
        #pragma unroll 8
        for (int c = 0; c < 64; c++) {
            float pv = P[c * 64 + t];
            p1 += w1[c] * pv;
            p2 += w2[c] * pv;
        }
        float nu = log1pf(expf(p1));        // softplus
        float th = tanhf(p2) * PIF;
        float d  = expf(-nu * dtb);
        float sa, ca;
        sincosf(th * dtb, &sa, &ca);
        fre += d * ca;
        fim += d * sa;
    }
    // store transposed [b][k][h] so the main kernel reads contiguously
    g_filtm1[(b * 64 + t) * 256 + h] = make_float2(fre - 1.0f, fim);
}

// ---------------- warp-cooperative 256-pt radix-2 DIT FFT (in smem) ------------
__device__ void fft256(float2* d, const float2* TW, int lane, bool inv) {
    // bit-reversal permutation (each unordered pair owned by exactly one lane)
    for (int i = lane; i < 256; i += 32) {
        int r = __brev(i) >> 24;
        if (r > i) { float2 tmp = d[i]; d[i] = d[r]; d[r] = tmp; }
    }
    __syncwarp();
    #pragma unroll
    for (int s = 0; s < 8; s++) {
        int half = 1 << s;
        for (int bt = lane; bt < 128; bt += 32) {
            int pos = bt & (half - 1);
            int i0  = ((bt >> s) << (s + 1)) + pos;
            int i1  = i0 + half;
            float2 w = TW[pos << (8 - s)];   // W_{2^{s+1}}^{pos}
            if (inv) w.y = -w.y;
            float2 a = d[i0];
            float2 bv = cmulf2(d[i1], w);
            d[i0] = make_float2(a.x + bv.x, a.y + bv.y);
            d[i1] = make_float2(a.x - bv.x, a.y - bv.y);
        }
        __syncwarp();
    }
}

// ---------------- fused main kernel: one CTA per (b,c) image -------------------
#define S_STRIDE 257
#define SMEM_BYTES ((64 * S_STRIDE + 512) * 8 + 8 * 512 * 4 + 8 * 512 * 8)

__global__ void __launch_bounds__(512, 1)
k_main(const float* __restrict__ x, float* __restrict__ out) {
    extern __shared__ char smem_raw[];
    float2* S  = (float2*)smem_raw;            // [64][257] complex tile A[k][h]
    float2* TW = S + 64 * S_STRIDE;            // 512 twiddles
    float*  XR = (float*)(TW + 512);           // 8 row buffers x 512 floats
    float2* GB = (float2*)(XR + 8 * 512);      // 8 buffers x (8m x 64j) complex

    int tid  = threadIdx.x;
    int bc   = blockIdx.x;
    int b    = bc >> 6;
    const float* xim = x   + (size_t)bc * (HH * WW);
    float*       oim = out + (size_t)bc * (HH * WW);

    if (tid < 512) TW[tid] = g_tw512[tid];
    __syncthreads();

    int pair = tid >> 6;        // 0..7 : 64-thread group, one row at a time
    int t64  = tid & 63;
    float*  xr = XR + pair * 512;
    float2* gb = GB + pair * 512;    // [m*64 + j]

    // ================= Phase A: partial forward W-DFT (512 -> 64 bins) ========
    for (int it = 0; it < 32; it++) {
        int h = it * 8 + pair;
        const float* row = xim + h * 512;
        #pragma unroll
        for (int i = t64; i < 512; i += 64) xr[i] = row[i];
        __syncthreads();

        // step1: real DFT8 across the 8 blocks, j = t64
        {
            int j = t64;
            float v0 = xr[j],       v1 = xr[64 + j],  v2 = xr[128 + j], v3 = xr[192 + j];
            float v4 = xr[256 + j], v5 = xr[320 + j], v6 = xr[384 + j], v7 = xr[448 + j];
            float e0 = v0 + v4, e1 = v1 + v5, e2 = v2 + v6, e3 = v3 + v7;
            float o0 = v0 - v4, o1 = v1 - v5, o2 = v2 - v6, o3 = v3 - v7;
            float s02 = e0 + e2, s13 = e1 + e3, d02 = e0 - e2, d13 = e1 - e3;
            const float R = 0.70710678118654752f;
            float t1 = R * (o1 - o3), t2 = R * (o1 + o3);
            gb[0 * 64 + j] = make_float2(s02 + s13, 0.f);
            gb[4 * 64 + j] = make_float2(s02 - s13, 0.f);
            gb[2 * 64 + j] = make_float2(d02, -d13);
            gb[6 * 64 + j] = make_float2(d02,  d13);
            gb[1 * 64 + j] = make_float2(o0 + t1, -o2 - t2);
            gb[3 * 64 + j] = make_float2(o0 - t1,  o2 - t2);
            gb[5 * 64 + j] = make_float2(o0 - t1, -(o2 - t2));
            gb[7 * 64 + j] = make_float2(o0 + t1,  o2 + t2);
        }
        __syncthreads();

        // step2: X[k] = sum_j W512^{kj} G[k&7][j], k = t64
        {
            int k = t64;
            const float2* gm = gb + (k & 7) * 64;
            float2 acc = make_float2(0.f, 0.f);
            int r = 0;
            #pragma unroll 8
            for (int j = 0; j < 64; j++) {
                float2 w = TW[r];
                float2 g = gm[j];
                acc.x += w.x * g.x - w.y * g.y;
                acc.y += w.x * g.y + w.y * g.x;
                r = (r + k) & 511;
            }
            S[k * S_STRIDE + h] = acc;
        }
        __syncthreads();
    }

    // ================= Phase B: FFT_H, multiply (filt-1), IFFT_H ==============
    {
        int wid  = tid >> 5;
        int lane = tid & 31;
        for (int k = wid; k < 64; k += 16) {
            float2* row = S + k * S_STRIDE;
            fft256(row, TW, lane, false);
            const float2* fg = &g_filtm1[(b * 64 + k) * 256];
            for (int i = lane; i < 256; i += 32)
                row[i] = cmulf2(row[i], fg[i]);
            __syncwarp();
            fft256(row, TW, lane, true);   // unnormalized inverse (scale folded later)
        }
    }
    __syncthreads();

    // ================= Phase C: partial inverse W-DFT, out = x + delta ========
    const float SCALE = 2.0f / (256.0f * 512.0f);
    for (int it = 0; it < 32; it++) {
        int h = it * 8 + pair;
        // Q stage: Q_m[j] = sum_a Z'_{8a+m} e^{+2pi i (8a+m) j /512}
        {
            int m = t64 >> 3, j0 = t64 & 7;
            float2 Z[8];
            #pragma unroll
            for (int a = 0; a < 8; a++) Z[a] = S[(8 * a + m) * S_STRIDE + h];
            if (m == 0) { Z[0].x *= 0.5f; Z[0].y *= 0.5f; }   // c_0 = 1 vs 2
            #pragma unroll
            for (int jj = 0; jj < 8; jj++) {
                int j = j0 + 8 * jj;
                int r = (m * j) & 511;
                int step = (8 * j) & 511;
                float2 q = make_float2(0.f, 0.f);
                #pragma unroll
                for (int a = 0; a < 8; a++) {
                    float2 w = TW[r];                 // conj -> e^{+i...}
                    q.x += Z[a].x * w.x + Z[a].y * w.y;
                    q.y += Z[a].y * w.x - Z[a].x * w.y;
                    r = (r + step) & 511;
                }
                gb[m * 64 + j] = q;
            }
        }
        __syncthreads();
        // output: delta[j+64u] = Re( sum_m e^{+2pi i m u/8} Q_m[j] )
        {
            int j = t64;
            float2 Q[8];
            #pragma unroll
            for (int m = 0; m < 8; m++) Q[m] = gb[m * 64 + j];
            const float* row  = xim + h * 512;
            float*       orow = oim + h * 512;
            #pragma unroll
            for (int u = 0; u < 8; u++) {
                float acc = 0.f;
                int mu = 0;
                #pragma unroll
                for (int m = 0; m < 8; m++) {
                    float2 w = TW[(mu & 7) << 6];     // e^{-2pi i (mu mod 8)/8}
                    acc += w.x * Q[m].x + w.y * Q[m].y;   // Re(conj(w)*Q)
                    mu += u;
                }
                int n = j + 64 * u;
                orow[n] = row[n] + acc * SCALE;
            }
        }
        __syncthreads();
    }
}

// ---------------- launcher ------------------------------------------------------
extern "C" void kernel_launch(void* const* d_in, const int* in_sizes, int n_in,
                              void* d_out, int out_size) {
    // identify inputs by element count (robust to ordering)
    const float* x = nullptr; const float* dt = nullptr;
    const float* cw = nullptr; const float* cb = nullptr;
    for (int i = 0; i < n_in; i++) {
        int s = in_sizes[i];
        if      (s == BATCH * CH * HH * WW) x  = (const float*)d_in[i];
        else if (s == BATCH)                dt = (const float*)d_in[i];
        else if (s == 64 * 64)              cw = (const float*)d_in[i];
        else if (s == 64)                   cb = (const float*)d_in[i];
    }
    float* out = (float*)d_out;

    cudaFuncSetAttribute(k_main, cudaFuncAttributeMaxDynamicSharedMemorySize,
                         SMEM_BYTES);

    k_tw  <<<1, 512>>>();
    k_pool<<<(BATCH * CH * HH * KF + 255) / 256, 256>>>(x);
    k_filt<<<BATCH * HH, 64>>>(cw, cb, dt);
    k_main<<<BATCH * CH, 512, SMEM_BYTES>>>(x, out);
}

// round 12
// speedup vs baseline: 2.9600x; 2.9600x over previous
#include <cuda_runtime.h>
#include <math.h>

#define BATCH 8
#define CH    64
#define HH    256
#define WW    512
#define KF    64      // W_FREQ low bins kept

// ---------------- device globals (scratch; no allocation allowed) -------------
__device__ float2 g_tw512[512];                       // e^{-2*pi*i*r/512}
__device__ float2 g_filtm1[BATCH * KF * HH];          // (filt-1), layout [b][k][h]
__device__ float  g_pooled[BATCH * CH * HH * KF];     // [b][c][h][wf]

// ---------------- tiny helpers -------------------------------------------------
__device__ __forceinline__ float2 cmulf2(float2 a, float2 b) {
    return make_float2(a.x * b.x - a.y * b.y, a.x * b.y + a.y * b.x);
}

// ---------------- twiddle init -------------------------------------------------
__global__ void k_tw() {
    int i = threadIdx.x;
    if (i < 512) {
        float s, c;
        sincospif((float)i / 256.0f, &s, &c);   // angle = 2*pi*i/512
        g_tw512[i] = make_float2(c, -s);
    }
}

// ---------------- pooled means: x.reshape(B,C,H,64,8).mean(-1) -----------------
__global__ void k_pool(const float* __restrict__ x) {
    int idx = blockIdx.x * blockDim.x + threadIdx.x;
    if (idx >= BATCH * CH * HH * KF) return;
    const float4* x4 = (const float4*)x;
    float4 a = x4[idx * 2];
    float4 b = x4[idx * 2 + 1];
    g_pooled[idx] = (a.x + a.y + a.z + a.w + b.x + b.y + b.z + b.w) * 0.125f;
}

// ---------------- filt-1 per (b, h): 64x64x64 matmul + nonlinearity ------------
__global__ void k_filt(const float* __restrict__ conv_w,
                       const float* __restrict__ conv_b,
                       const float* __restrict__ dt) {
    __shared__ float P[64 * 64];
    __shared__ float Wm[64 * 64];
    __shared__ float bs[64];
    int b = blockIdx.x >> 8;
    int h = blockIdx.x & 255;
    int t = threadIdx.x;

    for (int i = t; i < 4096; i += 64) Wm[i] = conv_w[i];
    bs[t] = conv_b[t];
    for (int c = 0; c < 64; c++)
        P[c * 64 + t] = g_pooled[((b * 64 + c) * 256 + h) * 64 + t];
    __syncthreads();

    float dtb = dt[b];
    float fre = 0.f, fim = 0.f;
    const float PIF = 3.14159265358979323846f;
    for (int r = 0; r < 32; r++) {
        float p1 = bs[r], p2 = bs[r + 32];
        const float* w1 = &Wm[r * 64];
        const float* w2 = &Wm[(r + 32) * 64];
        #pragma unroll 8
        for (int c = 0; c < 64; c++) {
            float pv = P[c * 64 + t];
            p1 += w1[c] * pv;
            p2 += w2[c] * pv;
        }
        float nu = log1pf(expf(p1));
        float th = tanhf(p2) * PIF;
        float d  = expf(-nu * dtb);
        float sa, ca;
        sincosf(th * dtb, &sa, &ca);
        fre += d * ca;
        fim += d * sa;
    }
    g_filtm1[(b * 64 + t) * 256 + h] = make_float2(fre - 1.0f, fim);
}

// ---------------- radix-4 Stockham 256-pt FFT (warp-cooperative, autosort) -----
// Data in A (contiguous 256 float2), scratch B. Result ends in A, natural order.
template <bool INV>
__device__ __forceinline__ void fft256_r4(float2* __restrict__ A,
                                          float2* __restrict__ B,
                                          const float2* __restrict__ TW,
                                          int lane) {
    const float sgn = INV ? -1.0f : 1.0f;
    // ---- stage 0: n=256, m=64, s=1 : A -> B (float4 contiguous stores)
    #pragma unroll
    for (int t2 = 0; t2 < 2; t2++) {
        int p = lane + 32 * t2;
        float2 a = A[p], b = A[p + 64], c = A[p + 128], d = A[p + 192];
        float2 w1 = TW[p << 1];
        if (INV) w1.y = -w1.y;
        float2 w2 = cmulf2(w1, w1);
        float2 w3 = cmulf2(w2, w1);
        float2 apc = make_float2(a.x + c.x, a.y + c.y);
        float2 amc = make_float2(a.x - c.x, a.y - c.y);
        float2 bpd = make_float2(b.x + d.x, b.y + d.y);
        float2 bmd = make_float2(b.x - d.x, b.y - d.y);
        float2 y0 = make_float2(apc.x + bpd.x, apc.y + bpd.y);
        float2 y2 = cmulf2(w2, make_float2(apc.x - bpd.x, apc.y - bpd.y));
        float2 y1 = cmulf2(w1, make_float2(amc.x + sgn * bmd.y, amc.y - sgn * bmd.x));
        float2 y3 = cmulf2(w3, make_float2(amc.x - sgn * bmd.y, amc.y + sgn * bmd.x));
        float4* dst4 = (float4*)(B + 4 * p);
        dst4[0] = make_float4(y0.x, y0.y, y1.x, y1.y);
        dst4[1] = make_float4(y2.x, y2.y, y3.x, y3.y);
    }
    __syncwarp();
    // ---- stage 1: n=64, m=16, s=4 : B -> A
    #pragma unroll
    for (int t2 = 0; t2 < 2; t2++) {
        int t = lane + 32 * t2;
        int p = t >> 2, q = t & 3;
        float2 a = B[t], b = B[t + 64], c = B[t + 128], d = B[t + 192];
        float2 w1 = TW[p << 3];
        if (INV) w1.y = -w1.y;
        float2 w2 = cmulf2(w1, w1);
        float2 w3 = cmulf2(w2, w1);
        float2 apc = make_float2(a.x + c.x, a.y + c.y);
        float2 amc = make_float2(a.x - c.x, a.y - c.y);
        float2 bpd = make_float2(b.x + d.x, b.y + d.y);
        float2 bmd = make_float2(b.x - d.x, b.y - d.y);
        int base = q + 16 * p;
        A[base]      = make_float2(apc.x + bpd.x, apc.y + bpd.y);
        A[base + 4]  = cmulf2(w1, make_float2(amc.x + sgn * bmd.y, amc.y - sgn * bmd.x));
        A[base + 8]  = cmulf2(w2, make_float2(apc.x - bpd.x, apc.y - bpd.y));
        A[base + 12] = cmulf2(w3, make_float2(amc.x - sgn * bmd.y, amc.y + sgn * bmd.x));
    }
    __syncwarp();
    // ---- stage 2: n=16, m=4, s=16 : A -> B
    #pragma unroll
    for (int t2 = 0; t2 < 2; t2++) {
        int t = lane + 32 * t2;
        int p = t >> 4, q = t & 15;
        float2 a = A[t], b = A[t + 64], c = A[t + 128], d = A[t + 192];
        float2 w1 = TW[p << 5];
        if (INV) w1.y = -w1.y;
        float2 w2 = cmulf2(w1, w1);
        float2 w3 = cmulf2(w2, w1);
        float2 apc = make_float2(a.x + c.x, a.y + c.y);
        float2 amc = make_float2(a.x - c.x, a.y - c.y);
        float2 bpd = make_float2(b.x + d.x, b.y + d.y);
        float2 bmd = make_float2(b.x - d.x, b.y - d.y);
        int base = q + 64 * p;
        B[base]      = make_float2(apc.x + bpd.x, apc.y + bpd.y);
        B[base + 16] = cmulf2(w1, make_float2(amc.x + sgn * bmd.y, amc.y - sgn * bmd.x));
        B[base + 32] = cmulf2(w2, make_float2(apc.x - bpd.x, apc.y - bpd.y));
        B[base + 48] = cmulf2(w3, make_float2(amc.x - sgn * bmd.y, amc.y + sgn * bmd.x));
    }
    __syncwarp();
    // ---- stage 3: n=4, m=1, s=64 : B -> A (twiddle = 1)
    #pragma unroll
    for (int t2 = 0; t2 < 2; t2++) {
        int q = lane + 32 * t2;
        float2 a = B[q], b = B[q + 64], c = B[q + 128], d = B[q + 192];
        float2 apc = make_float2(a.x + c.x, a.y + c.y);
        float2 amc = make_float2(a.x - c.x, a.y - c.y);
        float2 bpd = make_float2(b.x + d.x, b.y + d.y);
        float2 bmd = make_float2(b.x - d.x, b.y - d.y);
        A[q]       = make_float2(apc.x + bpd.x, apc.y + bpd.y);
        A[q + 64]  = make_float2(amc.x + sgn * bmd.y, amc.y - sgn * bmd.x);
        A[q + 128] = make_float2(apc.x - bpd.x, apc.y - bpd.y);
        A[q + 192] = make_float2(amc.x - sgn * bmd.y, amc.y + sgn * bmd.x);
    }
    __syncwarp();
}

// ---------------- fused main kernel: one CTA per (b,c) image -------------------
#define S_STRIDE 257
#define GB_STRIDE 66          // padded [m][j] stride: kills bank aliasing of m-bases
#define GB_PER_GRP (8 * GB_STRIDE)          // 528 float2 per 64-thread group
#define SMEM_BYTES (((64 * S_STRIDE + 512) + 8 * GB_PER_GRP) * 8)

__global__ void __launch_bounds__(512, 1)
k_main(const float* __restrict__ x, float* __restrict__ out) {
    extern __shared__ char smem_raw[];
    float2* S  = (float2*)smem_raw;            // [64][257] complex tile A[k][h]
    float2* TW = S + 64 * S_STRIDE;            // 512 twiddles
    float2* GB = TW + 512;                     // 8 groups x (8m x 66) complex

    int tid  = threadIdx.x;
    int bc   = blockIdx.x;
    int b    = bc >> 6;
    const float* xim = x   + (size_t)bc * (HH * WW);
    float*       oim = out + (size_t)bc * (HH * WW);

    TW[tid & 511] = g_tw512[tid & 511];
    __syncthreads();

    int pair = tid >> 6;        // 0..7 : 64-thread group
    int t64  = tid & 63;
    float2* gb = GB + pair * GB_PER_GRP;

    // ================= Phase A: partial forward W-DFT (512 -> 64 bins) ========
    for (int it = 0; it < 32; it++) {
        int h = it * 8 + pair;
        const float* row = xim + h * 512;
        // step1: real DFT8 across 8 blocks, direct from gmem (coalesced)
        {
            int j = t64;
            float v0 = row[j],       v1 = row[64 + j],  v2 = row[128 + j], v3 = row[192 + j];
            float v4 = row[256 + j], v5 = row[320 + j], v6 = row[384 + j], v7 = row[448 + j];
            float e0 = v0 + v4, e1 = v1 + v5, e2 = v2 + v6, e3 = v3 + v7;
            float o0 = v0 - v4, o1 = v1 - v5, o2 = v2 - v6, o3 = v3 - v7;
            float s02 = e0 + e2, s13 = e1 + e3, d02 = e0 - e2, d13 = e1 - e3;
            const float R = 0.70710678118654752f;
            float t1 = R * (o1 - o3), t2 = R * (o1 + o3);
            gb[0 * GB_STRIDE + j] = make_float2(s02 + s13, 0.f);
            gb[4 * GB_STRIDE + j] = make_float2(s02 - s13, 0.f);
            gb[2 * GB_STRIDE + j] = make_float2(d02, -d13);
            gb[6 * GB_STRIDE + j] = make_float2(d02,  d13);
            gb[1 * GB_STRIDE + j] = make_float2(o0 + t1, -o2 - t2);
            gb[3 * GB_STRIDE + j] = make_float2(o0 - t1,  o2 - t2);
            gb[5 * GB_STRIDE + j] = make_float2(o0 - t1, -(o2 - t2));
            gb[7 * GB_STRIDE + j] = make_float2(o0 + t1,  o2 + t2);
        }
        __syncthreads();
        // step2: X[k] = sum_j W512^{kj} G[k&7][j] — register twiddle recurrence
        {
            int k = t64;
            const float4* gm4 = (const float4*)(gb + (k & 7) * GB_STRIDE);
            float2 wk  = TW[k];
            float2 wk2 = cmulf2(wk, wk);
            float2 w0  = make_float2(1.f, 0.f);
            float2 acc = make_float2(0.f, 0.f);
            #pragma unroll 8
            for (int i = 0; i < 32; i++) {
                float4 g = gm4[i];
                acc.x += w0.x * g.x - w0.y * g.y;
                acc.y += w0.x * g.y + w0.y * g.x;
                float2 w1 = cmulf2(w0, wk);
                acc.x += w1.x * g.z - w1.y * g.w;
                acc.y += w1.x * g.w + w1.y * g.z;
                w0 = cmulf2(w0, wk2);
            }
            S[k * S_STRIDE + h] = acc;
        }
        __syncthreads();
    }

    // ================= Phase B: FFT_H, multiply (filt-1), IFFT_H ==============
    {
        int wid  = tid >> 5;
        int lane = tid & 31;
        float2* scr = GB + wid * 264;     // 16 warps x 264 <= 8*528
        for (int k = wid; k < 64; k += 16) {
            float2* row = S + k * S_STRIDE;
            fft256_r4<false>(row, scr, TW, lane);
            const float2* fg = &g_filtm1[(b * 64 + k) * 256];
            for (int i = lane; i < 256; i += 32)
                row[i] = cmulf2(row[i], fg[i]);
            __syncwarp();
            fft256_r4<true>(row, scr, TW, lane);   // unnormalized inverse
        }
    }
    __syncthreads();

    // ================= Phase C: partial inverse W-DFT, out = x + delta ========
    const float SCALE = 2.0f / (256.0f * 512.0f);
    const float RT = 0.70710678118654752f;
    const float C8[8] = {1.f,  RT, 0.f, -RT, -1.f, -RT, 0.f,  RT};
    const float S8[8] = {0.f,  RT, 1.f,  RT,  0.f, -RT, -1.f, -RT};
    for (int it = 0; it < 32; it++) {
        int h = it * 8 + pair;
        // Q stage: Q_m[j] = sum_a Z'_{8a+m} e^{+2pi i (8a+m) j /512}
        {
            int m = t64 >> 3, j0 = t64 & 7;
            float2 Z[8];
            #pragma unroll
            for (int a = 0; a < 8; a++) Z[a] = S[(8 * a + m) * S_STRIDE + h];
            if (m == 0) { Z[0].x *= 0.5f; Z[0].y *= 0.5f; }
            #pragma unroll
            for (int jj = 0; jj < 8; jj++) {
                int j = j0 + 8 * jj;
                float2 w  = TW[(m * j) & 511];
                float2 ws = TW[(8 * j) & 511];
                float2 q = make_float2(0.f, 0.f);
                #pragma unroll
                for (int a = 0; a < 8; a++) {
                    q.x += Z[a].x * w.x + Z[a].y * w.y;   // conj(w) * Z
                    q.y += Z[a].y * w.x - Z[a].x * w.y;
                    w = cmulf2(w, ws);
                }
                gb[m * GB_STRIDE + j] = q;
            }
        }
        __syncthreads();
        // output: delta[j+64u] = Re( sum_m e^{+2pi i m u/8} Q_m[j] ), W8 constants
        {
            int j = t64;
            float2 Q[8];
            #pragma unroll
            for (int m = 0; m < 8; m++) Q[m] = gb[m * GB_STRIDE + j];
            const float* rowx = xim + h * 512;
            float*       orow = oim + h * 512;
            #pragma unroll
            for (int u = 0; u < 8; u++) {
                float acc = 0.f;
                #pragma unroll
                for (int m = 0; m < 8; m++) {
                    const int t = (m * u) & 7;            // compile-time constant
                    acc += C8[t] * Q[m].x - S8[t] * Q[m].y;
                }
                int n = j + 64 * u;
                orow[n] = rowx[n] + acc * SCALE;
            }
        }
        __syncthreads();
    }
}

// ---------------- launcher ------------------------------------------------------
extern "C" void kernel_launch(void* const* d_in, const int* in_sizes, int n_in,
                              void* d_out, int out_size) {
    const float* x = nullptr; const float* dt = nullptr;
    const float* cw = nullptr; const float* cb = nullptr;
    for (int i = 0; i < n_in; i++) {
        int s = in_sizes[i];
        if      (s == BATCH * CH * HH * WW) x  = (const float*)d_in[i];
        else if (s == BATCH)                dt = (const float*)d_in[i];
        else if (s == 64 * 64)              cw = (const float*)d_in[i];
        else if (s == 64)                   cb = (const float*)d_in[i];
    }
    float* out = (float*)d_out;

    cudaFuncSetAttribute(k_main, cudaFuncAttributeMaxDynamicSharedMemorySize,
                         SMEM_BYTES);

    k_tw  <<<1, 512>>>();
    k_pool<<<(BATCH * CH * HH * KF + 255) / 256, 256>>>(x);
    k_filt<<<BATCH * HH, 64>>>(cw, cb, dt);
    k_main<<<BATCH * CH, 512, SMEM_BYTES>>>(x, out);
}

// round 13
// speedup vs baseline: 5.0775x; 1.7154x over previous
#include <cuda_runtime.h>
#include <math.h>

#define BATCH 8
#define CH    64
#define HH    256
#define WW    512
#define KF    64

// ---------------- device globals ----------------------------------------------
__device__ float2 g_tw512[512];                       // e^{-2*pi*i*r/512}
__device__ float2 g_filtm1[BATCH * KF * HH];          // (filt-1), [b][k][h]
__device__ float  g_pooled[BATCH * CH * HH * KF];     // [b][c][h][wf]

// ---------------- helpers ------------------------------------------------------
__device__ __forceinline__ float2 cmulf2(float2 a, float2 b) {
    return make_float2(a.x * b.x - a.y * b.y, a.x * b.y + a.y * b.x);
}
__device__ __forceinline__ float2 cmulcf2(float2 a, float2 b) {   // a * conj(b)
    return make_float2(a.x * b.x + a.y * b.y, a.y * b.x - a.x * b.y);
}
__device__ __forceinline__ float2 cadd(float2 a, float2 b){return make_float2(a.x+b.x, a.y+b.y);}
__device__ __forceinline__ float2 csub(float2 a, float2 b){return make_float2(a.x-b.x, a.y-b.y);}
// s=+1 -> i*a ; s=-1 -> -i*a
__device__ __forceinline__ float2 cmuli(float2 a, float s){ return make_float2(-s*a.y, s*a.x); }

// 8-point DFT in registers. F=1: kernel W8^{tj}=e^{-2pi i tj/8}. F=-1: conj kernel.
template<int F>
__device__ __forceinline__ void dft8(float2* z) {
    const float r = 0.70710678118654752f;
    float2 a  = cadd(z[0], z[4]), b  = csub(z[0], z[4]);
    float2 c  = cadd(z[2], z[6]), d  = csub(z[2], z[6]);
    float2 E0 = cadd(a, c), E2 = csub(a, c);
    float2 di = cmuli(d, (float)(-F));
    float2 E1 = cadd(b, di), E3 = csub(b, di);
    float2 a2 = cadd(z[1], z[5]), b2 = csub(z[1], z[5]);
    float2 c2 = cadd(z[3], z[7]), d2 = csub(z[3], z[7]);
    float2 O0 = cadd(a2, c2), O2 = csub(a2, c2);
    float2 d2i = cmuli(d2, (float)(-F));
    float2 O1 = cadd(b2, d2i), O3 = csub(b2, d2i);
    float2 T1 = make_float2(r * (O1.x + F * O1.y), r * (O1.y - F * O1.x));   // W8^1 * O1
    float2 T2 = cmuli(O2, (float)(-F));                                      // W8^2 * O2
    float2 T3 = make_float2(r * (-O3.x + F * O3.y), r * (-O3.y - F * O3.x)); // W8^3 * O3
    z[0] = cadd(E0, O0); z[4] = csub(E0, O0);
    z[1] = cadd(E1, T1); z[5] = csub(E1, T1);
    z[2] = cadd(E2, T2); z[6] = csub(E2, T2);
    z[3] = cadd(E3, T3); z[7] = csub(E3, T3);
}

// ---------------- twiddle init -------------------------------------------------
__global__ void k_tw() {
    int i = threadIdx.x;
    if (i < 512) {
        float s, c;
        sincospif((float)i / 256.0f, &s, &c);
        g_tw512[i] = make_float2(c, -s);
    }
}

// ---------------- pooled means -------------------------------------------------
__global__ void k_pool(const float* __restrict__ x) {
    int idx = blockIdx.x * blockDim.x + threadIdx.x;
    if (idx >= BATCH * CH * HH * KF) return;
    const float4* x4 = (const float4*)x;
    float4 a = x4[idx * 2];
    float4 b = x4[idx * 2 + 1];
    g_pooled[idx] = (a.x + a.y + a.z + a.w + b.x + b.y + b.z + b.w) * 0.125f;
}

// ---------------- filt-1 per (b, h) -------------------------------------------
__global__ void k_filt(const float* __restrict__ conv_w,
                       const float* __restrict__ conv_b,
                       const float* __restrict__ dt) {
    __shared__ float P[64 * 64];
    __shared__ float Wm[64 * 64];
    __shared__ float bs[64];
    int b = blockIdx.x >> 8;
    int h = blockIdx.x & 255;
    int t = threadIdx.x;

    for (int i = t; i < 4096; i += 64) Wm[i] = conv_w[i];
    bs[t] = conv_b[t];
    for (int c = 0; c < 64; c++)
        P[c * 64 + t] = g_pooled[((b * 64 + c) * 256 + h) * 64 + t];
    __syncthreads();

    float dtb = dt[b];
    float fre = 0.f, fim = 0.f;
    const float PIF = 3.14159265358979323846f;
    for (int r = 0; r < 32; r++) {
        float p1 = bs[r], p2 = bs[r + 32];
        const float* w1 = &Wm[r * 64];
        const float* w2 = &Wm[(r + 32) * 64];
        #pragma unroll 8
        for (int c = 0; c < 64; c++) {
            float pv = P[c * 64 + t];
            p1 += w1[c] * pv;
            p2 += w2[c] * pv;
        }
        // decay = exp(-softplus(p1)*dt) = (1+e^p1)^(-dt)
        float e   = __expf(p1);
        float dcy = exp2f(-dtb * __log2f(1.f + e));
        float th  = tanhf(p2) * PIF;
        float sa, ca;
        __sincosf(th * dtb, &sa, &ca);
        fre += dcy * ca;
        fim += dcy * sa;
    }
    g_filtm1[(b * 64 + t) * 256 + h] = make_float2(fre - 1.0f, fim);
}

// ---------------- radix-4 Stockham 256-pt FFT (warp-cooperative) ---------------
template <bool INV>
__device__ __forceinline__ void fft256_r4(float2* __restrict__ A,
                                          float2* __restrict__ B,
                                          const float2* __restrict__ TW,
                                          int lane) {
    const float sgn = INV ? -1.0f : 1.0f;
    #pragma unroll
    for (int t2 = 0; t2 < 2; t2++) {
        int p = lane + 32 * t2;
        float2 a = A[p], b = A[p + 64], c = A[p + 128], d = A[p + 192];
        float2 w1 = TW[p << 1];
        if (INV) w1.y = -w1.y;
        float2 w2 = cmulf2(w1, w1);
        float2 w3 = cmulf2(w2, w1);
        float2 apc = cadd(a, c), amc = csub(a, c);
        float2 bpd = cadd(b, d), bmd = csub(b, d);
        float2 y0 = cadd(apc, bpd);
        float2 y2 = cmulf2(w2, csub(apc, bpd));
        float2 y1 = cmulf2(w1, make_float2(amc.x + sgn * bmd.y, amc.y - sgn * bmd.x));
        float2 y3 = cmulf2(w3, make_float2(amc.x - sgn * bmd.y, amc.y + sgn * bmd.x));
        float4* dst4 = (float4*)(B + 4 * p);
        dst4[0] = make_float4(y0.x, y0.y, y1.x, y1.y);
        dst4[1] = make_float4(y2.x, y2.y, y3.x, y3.y);
    }
    __syncwarp();
    #pragma unroll
    for (int t2 = 0; t2 < 2; t2++) {
        int t = lane + 32 * t2;
        int p = t >> 2, q = t & 3;
        float2 a = B[t], b = B[t + 64], c = B[t + 128], d = B[t + 192];
        float2 w1 = TW[p << 3];
        if (INV) w1.y = -w1.y;
        float2 w2 = cmulf2(w1, w1);
        float2 w3 = cmulf2(w2, w1);
        float2 apc = cadd(a, c), amc = csub(a, c);
        float2 bpd = cadd(b, d), bmd = csub(b, d);
        int base = q + 16 * p;
        A[base]      = cadd(apc, bpd);
        A[base + 4]  = cmulf2(w1, make_float2(amc.x + sgn * bmd.y, amc.y - sgn * bmd.x));
        A[base + 8]  = cmulf2(w2, csub(apc, bpd));
        A[base + 12] = cmulf2(w3, make_float2(amc.x - sgn * bmd.y, amc.y + sgn * bmd.x));
    }
    __syncwarp();
    #pragma unroll
    for (int t2 = 0; t2 < 2; t2++) {
        int t = lane + 32 * t2;
        int p = t >> 4, q = t & 15;
        float2 a = A[t], b = A[t + 64], c = A[t + 128], d = A[t + 192];
        float2 w1 = TW[p << 5];
        if (INV) w1.y = -w1.y;
        float2 w2 = cmulf2(w1, w1);
        float2 w3 = cmulf2(w2, w1);
        float2 apc = cadd(a, c), amc = csub(a, c);
        float2 bpd = cadd(b, d), bmd = csub(b, d);
        int base = q + 64 * p;
        B[base]      = cadd(apc, bpd);
        B[base + 16] = cmulf2(w1, make_float2(amc.x + sgn * bmd.y, amc.y - sgn * bmd.x));
        B[base + 32] = cmulf2(w2, csub(apc, bpd));
        B[base + 48] = cmulf2(w3, make_float2(amc.x - sgn * bmd.y, amc.y + sgn * bmd.x));
    }
    __syncwarp();
    #pragma unroll
    for (int t2 = 0; t2 < 2; t2++) {
        int q = lane + 32 * t2;
        float2 a = B[q], b = B[q + 64], c = B[q + 128], d = B[q + 192];
        float2 apc = cadd(a, c), amc = csub(a, c);
        float2 bpd = cadd(b, d), bmd = csub(b, d);
        A[q]       = cadd(apc, bpd);
        A[q + 64]  = make_float2(amc.x + sgn * bmd.y, amc.y - sgn * bmd.x);
        A[q + 128] = csub(apc, bpd);
        A[q + 192] = make_float2(amc.x - sgn * bmd.y, amc.y + sgn * bmd.x);
    }
    __syncwarp();
}

// ---------------- fused main kernel --------------------------------------------
#define S_STRIDE 257
#define G_STRIDE 68                               // complex stride per m-row
#define GRP_PER  (8 * G_STRIDE)                   // 544 float2 per 64-thread group
#define SMEM_BYTES ((64 * S_STRIDE + 512 + 8 * GRP_PER) * 8)

// group barrier: 2 warps (64 threads), ids 1..8
#define BARG() asm volatile("bar.sync %0, %1;" :: "r"(pair + 1), "r"(64) : "memory")

__global__ void __launch_bounds__(512, 1)
k_main(const float* __restrict__ x, float* __restrict__ out) {
    extern __shared__ char smem_raw[];
    float2* S   = (float2*)smem_raw;            // [64][257] tile X[k][h]
    float2* TW  = S + 64 * S_STRIDE;            // 512 twiddles
    float2* GRP = TW + 512;                     // 8 groups x 544

    int tid  = threadIdx.x;
    int bc   = blockIdx.x;
    int b    = bc >> 6;
    const float* xim = x   + (size_t)bc * (HH * WW);
    float*       oim = out + (size_t)bc * (HH * WW);

    TW[tid & 511] = g_tw512[tid & 511];
    __syncthreads();

    int pair = tid >> 6;        // 0..7 group id
    int t64  = tid & 63;
    float2* grp = GRP + pair * GRP_PER;
    int m8  = t64 >> 3;         // m for passes
    int j08 = t64 & 7;          // j0 for passes

    // ================= Phase A: partial forward W-DFT (512 -> 64 bins) ========
    float v[8];
    {
        const float* row0 = xim + pair * 512;
        #pragma unroll
        for (int u = 0; u < 8; u++) v[u] = row0[t64 + 64 * u];
    }
    for (int it = 0; it < 32; it++) {
        int h = it * 8 + pair;
        // ---- step1: real DFT8 across the 8 blocks (j = t64), from registers
        {
            int j = t64;
            float e0 = v[0] + v[4], e1 = v[1] + v[5], e2 = v[2] + v[6], e3 = v[3] + v[7];
            float o0 = v[0] - v[4], o1 = v[1] - v[5], o2 = v[2] - v[6], o3 = v[3] - v[7];
            float s02 = e0 + e2, s13 = e1 + e3, d02 = e0 - e2, d13 = e1 - e3;
            const float R = 0.70710678118654752f;
            float t1 = R * (o1 - o3), t2 = R * (o1 + o3);
            grp[0 * G_STRIDE + j] = make_float2(s02 + s13, 0.f);
            grp[4 * G_STRIDE + j] = make_float2(s02 - s13, 0.f);
            grp[2 * G_STRIDE + j] = make_float2(d02, -d13);
            grp[6 * G_STRIDE + j] = make_float2(d02,  d13);
            grp[1 * G_STRIDE + j] = make_float2(o0 + t1, -o2 - t2);
            grp[3 * G_STRIDE + j] = make_float2(o0 - t1,  o2 - t2);
            grp[5 * G_STRIDE + j] = make_float2(o0 - t1, -(o2 - t2));
            grp[7 * G_STRIDE + j] = make_float2(o0 + t1,  o2 + t2);
        }
        BARG();
        // prefetch next row into v (overlaps with pass1/pass2 compute)
        if (it < 31) {
            const float* nr = xim + (h + 8) * 512;
            #pragma unroll
            for (int u = 0; u < 8; u++) v[u] = nr[t64 + 64 * u];
        }
        // ---- pass1: P[m][j0][t] = DFT8_{j1}( W64^{m j1} G[m][j0+8j1] )
        {
            float2 wm = TW[8 * m8];
            float2 w  = make_float2(1.f, 0.f);
            float2 z[8];
            #pragma unroll
            for (int j1 = 0; j1 < 8; j1++) {
                float2 g = grp[m8 * G_STRIDE + j08 + 8 * j1];
                z[j1] = cmulf2(g, w);
                w = cmulf2(w, wm);
            }
            dft8<1>(z);
            BARG();   // all G reads done before overwrite
            #pragma unroll
            for (int t = 0; t < 8; t++)
                grp[m8 * G_STRIDE + t * 8 + j08] = z[t];
        }
        BARG();
        // ---- pass2: X[k] = sum_{j0} W512^{k j0} P[k&7][j0][k>>3]
        {
            int k = t64, mm = k & 7, tt = k >> 3;
            const float4* pp = (const float4*)(grp + mm * G_STRIDE + tt * 8);
            float2 wk = TW[k];
            float2 w  = make_float2(1.f, 0.f);
            float2 acc = make_float2(0.f, 0.f);
            #pragma unroll
            for (int q = 0; q < 4; q++) {
                float4 g2 = pp[q];
                acc.x += w.x * g2.x - w.y * g2.y;
                acc.y += w.x * g2.y + w.y * g2.x;
                w = cmulf2(w, wk);
                acc.x += w.x * g2.z - w.y * g2.w;
                acc.y += w.x * g2.w + w.y * g2.z;
                w = cmulf2(w, wk);
            }
            S[k * S_STRIDE + h] = acc;
        }
        BARG();
    }
    __syncthreads();

    // ================= Phase B: FFT_H, multiply (filt-1), IFFT_H ==============
    {
        int wid  = tid >> 5;
        int lane = tid & 31;
        float2* scr = GRP + wid * 272;     // 16 warps x 272 = 4352 = 8*544
        for (int k = wid; k < 64; k += 16) {
            float2* row = S + k * S_STRIDE;
            fft256_r4<false>(row, scr, TW, lane);
            const float2* fg = &g_filtm1[(b * 64 + k) * 256];
            for (int i = lane; i < 256; i += 32)
                row[i] = cmulf2(row[i], fg[i]);
            __syncwarp();
            fft256_r4<true>(row, scr, TW, lane);
        }
    }
    __syncthreads();

    // ================= Phase C: partial inverse W-DFT, out = x + delta ========
    const float SCALE = 2.0f / (256.0f * 512.0f);
    const float RT = 0.70710678118654752f;
    const float C8[8] = {1.f,  RT, 0.f, -RT, -1.f, -RT, 0.f,  RT};
    const float S8[8] = {0.f,  RT, 1.f,  RT,  0.f, -RT, -1.f, -RT};
    for (int it = 0; it < 32; it++) {
        int h = it * 8 + pair;
        const float* rowx = xim + h * 512;
        float xv[8];
        #pragma unroll
        for (int u = 0; u < 8; u++) xv[u] = rowx[t64 + 64 * u];
        // ---- pass1: R = IDFT8_a( conj(W64^{a j0}) Z[8a+m] ); Q = conj(W512^{m j}) R
        {
            float2 ws = TW[8 * j08];
            float2 w  = make_float2(1.f, 0.f);
            float2 z[8];
            #pragma unroll
            for (int a = 0; a < 8; a++) {
                float2 zz = S[(8 * a + m8) * S_STRIDE + h];
                z[a] = cmulcf2(zz, w);
                w = cmulf2(w, ws);
            }
            if (m8 == 0) { z[0].x *= 0.5f; z[0].y *= 0.5f; }
            dft8<-1>(z);
            float2 wq  = TW[(m8 * j08) & 511];
            float2 wqs = TW[8 * m8];
            #pragma unroll
            for (int j1 = 0; j1 < 8; j1++) {
                grp[m8 * G_STRIDE + j08 + 8 * j1] = cmulcf2(z[j1], wq);
                wq = cmulf2(wq, wqs);
            }
        }
        BARG();
        // ---- output: delta[j+64u] = Re( sum_m W8^{-mu} Q_m[j] )
        {
            int j = t64;
            float2 Q[8];
            #pragma unroll
            for (int mm = 0; mm < 8; mm++) Q[mm] = grp[mm * G_STRIDE + j];
            float* orow = oim + h * 512;
            #pragma unroll
            for (int u = 0; u < 8; u++) {
                float acc = 0.f;
                #pragma unroll
                for (int mm = 0; mm < 8; mm++) {
                    const int t = (mm * u) & 7;
                    acc += C8[t] * Q[mm].x - S8[t] * Q[mm].y;
                }
                orow[j + 64 * u] = xv[u] + acc * SCALE;
            }
        }
        BARG();
    }
}

// ---------------- launcher ------------------------------------------------------
extern "C" void kernel_launch(void* const* d_in, const int* in_sizes, int n_in,
                              void* d_out, int out_size) {
    const float* x = nullptr; const float* dt = nullptr;
    const float* cw = nullptr; const float* cb = nullptr;
    for (int i = 0; i < n_in; i++) {
        int s = in_sizes[i];
        if      (s == BATCH * CH * HH * WW) x  = (const float*)d_in[i];
        else if (s == BATCH)                dt = (const float*)d_in[i];
        else if (s == 64 * 64)              cw = (const float*)d_in[i];
        else if (s == 64)                   cb = (const float*)d_in[i];
    }
    float* out = (float*)d_out;

    cudaFuncSetAttribute(k_main, cudaFuncAttributeMaxDynamicSharedMemorySize,
                         SMEM_BYTES);

    k_tw  <<<1, 512>>>();
    k_pool<<<(BATCH * CH * HH * KF + 255) / 256, 256>>>(x);
    k_filt<<<BATCH * HH, 64>>>(cw, cb, dt);
    k_main<<<BATCH * CH, 512, SMEM_BYTES>>>(x, out);
}

// round 14
// speedup vs baseline: 5.4504x; 1.0734x over previous
#include <cuda_runtime.h>
#include <math.h>

#define BATCH 8
#define CH    64
#define HH    256
#define WW    512
#define KF    64

// ---------------- device globals ----------------------------------------------
__device__ float2 g_tw512[512];                       // e^{-2*pi*i*r/512}
__device__ float2 g_filtm1[BATCH * KF * HH];          // (filt-1), [b][k][h]

// ---------------- helpers ------------------------------------------------------
__device__ __forceinline__ float2 cmulf2(float2 a, float2 b) {
    return make_float2(a.x * b.x - a.y * b.y, a.x * b.y + a.y * b.x);
}
__device__ __forceinline__ float2 cmulcf2(float2 a, float2 b) {   // a * conj(b)
    return make_float2(a.x * b.x + a.y * b.y, a.y * b.x - a.x * b.y);
}
__device__ __forceinline__ float2 cadd(float2 a, float2 b){return make_float2(a.x+b.x, a.y+b.y);}
__device__ __forceinline__ float2 csub(float2 a, float2 b){return make_float2(a.x-b.x, a.y-b.y);}
__device__ __forceinline__ float2 cmuli(float2 a, float s){ return make_float2(-s*a.y, s*a.x); }

// 8-point DFT in registers. F=1: kernel e^{-2pi i tj/8}. F=-1: conj kernel.
template<int F>
__device__ __forceinline__ void dft8(float2* z) {
    const float r = 0.70710678118654752f;
    float2 a  = cadd(z[0], z[4]), b  = csub(z[0], z[4]);
    float2 c  = cadd(z[2], z[6]), d  = csub(z[2], z[6]);
    float2 E0 = cadd(a, c), E2 = csub(a, c);
    float2 di = cmuli(d, (float)(-F));
    float2 E1 = cadd(b, di), E3 = csub(b, di);
    float2 a2 = cadd(z[1], z[5]), b2 = csub(z[1], z[5]);
    float2 c2 = cadd(z[3], z[7]), d2 = csub(z[3], z[7]);
    float2 O0 = cadd(a2, c2), O2 = csub(a2, c2);
    float2 d2i = cmuli(d2, (float)(-F));
    float2 O1 = cadd(b2, d2i), O3 = csub(b2, d2i);
    float2 T1 = make_float2(r * (O1.x + F * O1.y), r * (O1.y - F * O1.x));
    float2 T2 = cmuli(O2, (float)(-F));
    float2 T3 = make_float2(r * (-O3.x + F * O3.y), r * (-O3.y - F * O3.x));
    z[0] = cadd(E0, O0); z[4] = csub(E0, O0);
    z[1] = cadd(E1, T1); z[5] = csub(E1, T1);
    z[2] = cadd(E2, T2); z[6] = csub(E2, T2);
    z[3] = cadd(E3, T3); z[7] = csub(E3, T3);
}

// ---------------- twiddle init -------------------------------------------------
__global__ void k_tw() {
    int i = threadIdx.x;
    if (i < 512) {
        float s, c;
        sincospif((float)i / 256.0f, &s, &c);
        g_tw512[i] = make_float2(c, -s);
    }
}

// ---------------- fused pool + filt: one block = (b, 8 h values) ---------------
// 512 threads = 8 groups x 64 (wf). Pools x directly (no intermediate global).
#define FILT_SMEM ((4096 + 64 + 8 * 4096) * 4)
__global__ void __launch_bounds__(512, 1)
k_filt(const float* __restrict__ x,
       const float* __restrict__ conv_w,
       const float* __restrict__ conv_b,
       const float* __restrict__ dt) {
    extern __shared__ float fsm[];
    float* Wm = fsm;               // 4096
    float* bs = Wm + 4096;         // 64
    float* P  = bs + 64;           // 8 groups x 4096  : P_g[c*64+wf]

    int tid = threadIdx.x;
    int g   = tid >> 6;            // h-group 0..7
    int wf  = tid & 63;
    int b   = blockIdx.x >> 5;
    int h   = (blockIdx.x & 31) * 8 + g;

    for (int i = tid; i < 4096; i += 512) Wm[i] = conv_w[i];
    if (tid < 64) bs[tid] = conv_b[tid];

    // pool: P_g[c][wf] = mean of 8 consecutive x values
    float* Pg = P + g * 4096;
    const float4* xb = (const float4*)(x + ((size_t)(b * 64) * 256 + h) * 512);
    // row (b,c,h): starts at float4 index ((c*256)*512)/4 = c*32768 ; wf covers 8 floats = 2 float4
    for (int c = 0; c < 64; c++) {
        float4 a0 = xb[c * 32768 + wf * 2];
        float4 a1 = xb[c * 32768 + wf * 2 + 1];
        Pg[c * 64 + wf] = (a0.x + a0.y + a0.z + a0.w + a1.x + a1.y + a1.z + a1.w) * 0.125f;
    }
    __syncthreads();

    float dtb = dt[b];
    float fre = 0.f, fim = 0.f;
    const float PIF = 3.14159265358979323846f;
    for (int r = 0; r < 32; r++) {
        float p1 = bs[r], p2 = bs[r + 32];
        const float* w1 = &Wm[r * 64];
        const float* w2 = &Wm[(r + 32) * 64];
        #pragma unroll 8
        for (int c = 0; c < 64; c++) {
            float pv = Pg[c * 64 + wf];
            p1 += w1[c] * pv;
            p2 += w2[c] * pv;
        }
        // decay = (1+e^p1)^(-dt)
        float e   = __expf(p1);
        float dcy = exp2f(-dtb * __log2f(1.f + e));
        // tanh via exp
        float e2  = __expf(2.f * p2);
        float th  = __fdividef(e2 - 1.f, e2 + 1.f) * PIF;
        float sa, ca;
        __sincosf(th * dtb, &sa, &ca);
        fre += dcy * ca;
        fim += dcy * sa;
    }
    g_filtm1[(b * 64 + wf) * 256 + h] = make_float2(fre - 1.0f, fim);
}

// ---------------- radix-4 Stockham 256-pt FFT (warp-cooperative) ---------------
template <bool INV>
__device__ __forceinline__ void fft256_r4(float2* __restrict__ A,
                                          float2* __restrict__ B,
                                          const float2* __restrict__ TW,
                                          int lane) {
    const float sgn = INV ? -1.0f : 1.0f;
    #pragma unroll
    for (int t2 = 0; t2 < 2; t2++) {
        int p = lane + 32 * t2;
        float2 a = A[p], b = A[p + 64], c = A[p + 128], d = A[p + 192];
        float2 w1 = TW[p << 1];
        if (INV) w1.y = -w1.y;
        float2 w2 = cmulf2(w1, w1);
        float2 w3 = cmulf2(w2, w1);
        float2 apc = cadd(a, c), amc = csub(a, c);
        float2 bpd = cadd(b, d), bmd = csub(b, d);
        float2 y0 = cadd(apc, bpd);
        float2 y2 = cmulf2(w2, csub(apc, bpd));
        float2 y1 = cmulf2(w1, make_float2(amc.x + sgn * bmd.y, amc.y - sgn * bmd.x));
        float2 y3 = cmulf2(w3, make_float2(amc.x - sgn * bmd.y, amc.y + sgn * bmd.x));
        float4* dst4 = (float4*)(B + 4 * p);
        dst4[0] = make_float4(y0.x, y0.y, y1.x, y1.y);
        dst4[1] = make_float4(y2.x, y2.y, y3.x, y3.y);
    }
    __syncwarp();
    #pragma unroll
    for (int t2 = 0; t2 < 2; t2++) {
        int t = lane + 32 * t2;
        int p = t >> 2, q = t & 3;
        float2 a = B[t], b = B[t + 64], c = B[t + 128], d = B[t + 192];
        float2 w1 = TW[p << 3];
        if (INV) w1.y = -w1.y;
        float2 w2 = cmulf2(w1, w1);
        float2 w3 = cmulf2(w2, w1);
        float2 apc = cadd(a, c), amc = csub(a, c);
        float2 bpd = cadd(b, d), bmd = csub(b, d);
        int base = q + 16 * p;
        A[base]      = cadd(apc, bpd);
        A[base + 4]  = cmulf2(w1, make_float2(amc.x + sgn * bmd.y, amc.y - sgn * bmd.x));
        A[base + 8]  = cmulf2(w2, csub(apc, bpd));
        A[base + 12] = cmulf2(w3, make_float2(amc.x - sgn * bmd.y, amc.y + sgn * bmd.x));
    }
    __syncwarp();
    #pragma unroll
    for (int t2 = 0; t2 < 2; t2++) {
        int t = lane + 32 * t2;
        int p = t >> 4, q = t & 15;
        float2 a = A[t], b = A[t + 64], c = A[t + 128], d = A[t + 192];
        float2 w1 = TW[p << 5];
        if (INV) w1.y = -w1.y;
        float2 w2 = cmulf2(w1, w1);
        float2 w3 = cmulf2(w2, w1);
        float2 apc = cadd(a, c), amc = csub(a, c);
        float2 bpd = cadd(b, d), bmd = csub(b, d);
        int base = q + 64 * p;
        B[base]      = cadd(apc, bpd);
        B[base + 16] = cmulf2(w1, make_float2(amc.x + sgn * bmd.y, amc.y - sgn * bmd.x));
        B[base + 32] = cmulf2(w2, csub(apc, bpd));
        B[base + 48] = cmulf2(w3, make_float2(amc.x - sgn * bmd.y, amc.y + sgn * bmd.x));
    }
    __syncwarp();
    #pragma unroll
    for (int t2 = 0; t2 < 2; t2++) {
        int q = lane + 32 * t2;
        float2 a = B[q], b = B[q + 64], c = B[q + 128], d = B[q + 192];
        float2 apc = cadd(a, c), amc = csub(a, c);
        float2 bpd = cadd(b, d), bmd = csub(b, d);
        A[q]       = cadd(apc, bpd);
        A[q + 64]  = make_float2(amc.x + sgn * bmd.y, amc.y - sgn * bmd.x);
        A[q + 128] = csub(apc, bpd);
        A[q + 192] = make_float2(amc.x - sgn * bmd.y, amc.y + sgn * bmd.x);
    }
    __syncwarp();
}

// ---------------- fused main kernel: 1024 threads, 16 row-groups ----------------
#define S_STRIDE 257
#define G_STRIDE 68
#define GRP_PER  (8 * G_STRIDE)                   // 544 float2 per 64-thread group
#define NGRP 16
#define SMEM_BYTES ((64 * S_STRIDE + 512 + NGRP * GRP_PER) * 8)

// two groups share one named barrier (ids 1..8), count 128
#define BARG() asm volatile("bar.sync %0, %1;" :: "r"((pair >> 1) + 1), "r"(128) : "memory")

__global__ void __launch_bounds__(1024, 1)
k_main(const float* __restrict__ x, float* __restrict__ out) {
    extern __shared__ char smem_raw[];
    float2* S   = (float2*)smem_raw;            // [64][257] tile X[k][h]
    float2* TW  = S + 64 * S_STRIDE;            // 512 twiddles
    float2* GRP = TW + 512;                     // 16 groups x 544

    int tid  = threadIdx.x;
    int bc   = blockIdx.x;
    int b    = bc >> 6;
    const float* xim = x   + (size_t)bc * (HH * WW);
    float*       oim = out + (size_t)bc * (HH * WW);

    if (tid < 512) TW[tid] = g_tw512[tid];
    __syncthreads();

    int pair = tid >> 6;        // 0..15 group id
    int t64  = tid & 63;
    float2* grp = GRP + pair * GRP_PER;
    int m8  = t64 >> 3;
    int j08 = t64 & 7;

    // ================= Phase A: partial forward W-DFT (512 -> 64 bins) ========
    float v[8];
    {
        const float* row0 = xim + pair * 512;
        #pragma unroll
        for (int u = 0; u < 8; u++) v[u] = row0[t64 + 64 * u];
    }
    for (int it = 0; it < 16; it++) {
        int h = it * 16 + pair;
        // ---- step1: real DFT8 across the 8 blocks (j = t64)
        {
            int j = t64;
            float e0 = v[0] + v[4], e1 = v[1] + v[5], e2 = v[2] + v[6], e3 = v[3] + v[7];
            float o0 = v[0] - v[4], o1 = v[1] - v[5], o2 = v[2] - v[6], o3 = v[3] - v[7];
            float s02 = e0 + e2, s13 = e1 + e3, d02 = e0 - e2, d13 = e1 - e3;
            const float R = 0.70710678118654752f;
            float t1 = R * (o1 - o3), t2 = R * (o1 + o3);
            grp[0 * G_STRIDE + j] = make_float2(s02 + s13, 0.f);
            grp[4 * G_STRIDE + j] = make_float2(s02 - s13, 0.f);
            grp[2 * G_STRIDE + j] = make_float2(d02, -d13);
            grp[6 * G_STRIDE + j] = make_float2(d02,  d13);
            grp[1 * G_STRIDE + j] = make_float2(o0 + t1, -o2 - t2);
            grp[3 * G_STRIDE + j] = make_float2(o0 - t1,  o2 - t2);
            grp[5 * G_STRIDE + j] = make_float2(o0 - t1, -(o2 - t2));
            grp[7 * G_STRIDE + j] = make_float2(o0 + t1,  o2 + t2);
        }
        BARG();
        // prefetch next row
        if (it < 15) {
            const float* nr = xim + (h + 16) * 512;
            #pragma unroll
            for (int u = 0; u < 8; u++) v[u] = nr[t64 + 64 * u];
        }
        // ---- pass1: P[m][j0][t] = DFT8_{j1}( W64^{m j1} G[m][j0+8j1] )
        {
            float2 wm = TW[8 * m8];
            float2 w  = make_float2(1.f, 0.f);
            float2 z[8];
            #pragma unroll
            for (int j1 = 0; j1 < 8; j1++) {
                float2 g = grp[m8 * G_STRIDE + j08 + 8 * j1];
                z[j1] = cmulf2(g, w);
                w = cmulf2(w, wm);
            }
            dft8<1>(z);
            BARG();
            #pragma unroll
            for (int t = 0; t < 8; t++)
                grp[m8 * G_STRIDE + t * 8 + j08] = z[t];
        }
        BARG();
        // ---- pass2: X[k] = sum_{j0} W512^{k j0} P[k&7][j0][k>>3]
        {
            int k = t64, mm = k & 7, tt = k >> 3;
            const float4* pp = (const float4*)(grp + mm * G_STRIDE + tt * 8);
            float2 wk = TW[k];
            float2 w  = make_float2(1.f, 0.f);
            float2 acc = make_float2(0.f, 0.f);
            #pragma unroll
            for (int q = 0; q < 4; q++) {
                float4 g2 = pp[q];
                acc.x += w.x * g2.x - w.y * g2.y;
                acc.y += w.x * g2.y + w.y * g2.x;
                w = cmulf2(w, wk);
                acc.x += w.x * g2.z - w.y * g2.w;
                acc.y += w.x * g2.w + w.y * g2.z;
                w = cmulf2(w, wk);
            }
            S[k * S_STRIDE + h] = acc;
        }
        BARG();
    }
    __syncthreads();

    // ================= Phase B: FFT_H, multiply (filt-1), IFFT_H ==============
    {
        int wid  = tid >> 5;                // 0..31
        int lane = tid & 31;
        float2* scr = GRP + wid * 272;      // 32 warps x 272 = 8704 = 16*544
        for (int k = wid; k < 64; k += 32) {
            float2* row = S + k * S_STRIDE;
            fft256_r4<false>(row, scr, TW, lane);
            const float2* fg = &g_filtm1[(b * 64 + k) * 256];
            for (int i = lane; i < 256; i += 32)
                row[i] = cmulf2(row[i], fg[i]);
            __syncwarp();
            fft256_r4<true>(row, scr, TW, lane);
        }
    }
    __syncthreads();

    // ================= Phase C: partial inverse W-DFT, out = x + delta ========
    const float SCALE = 2.0f / (256.0f * 512.0f);
    const float RT = 0.70710678118654752f;
    const float C8[8] = {1.f,  RT, 0.f, -RT, -1.f, -RT, 0.f,  RT};
    const float S8[8] = {0.f,  RT, 1.f,  RT,  0.f, -RT, -1.f, -RT};
    for (int it = 0; it < 16; it++) {
        int h = it * 16 + pair;
        const float* rowx = xim + h * 512;
        float xv[8];
        #pragma unroll
        for (int u = 0; u < 8; u++) xv[u] = rowx[t64 + 64 * u];
        // ---- pass1
        {
            float2 ws = TW[8 * j08];
            float2 w  = make_float2(1.f, 0.f);
            float2 z[8];
            #pragma unroll
            for (int a = 0; a < 8; a++) {
                float2 zz = S[(8 * a + m8) * S_STRIDE + h];
                z[a] = cmulcf2(zz, w);
                w = cmulf2(w, ws);
            }
            if (m8 == 0) { z[0].x *= 0.5f; z[0].y *= 0.5f; }
            dft8<-1>(z);
            float2 wq  = TW[(m8 * j08) & 511];
            float2 wqs = TW[8 * m8];
            #pragma unroll
            for (int j1 = 0; j1 < 8; j1++) {
                grp[m8 * G_STRIDE + j08 + 8 * j1] = cmulcf2(z[j1], wq);
                wq = cmulf2(wq, wqs);
            }
        }
        BARG();
        // ---- output
        {
            int j = t64;
            float2 Q[8];
            #pragma unroll
            for (int mm = 0; mm < 8; mm++) Q[mm] = grp[mm * G_STRIDE + j];
            float* orow = oim + h * 512;
            #pragma unroll
            for (int u = 0; u < 8; u++) {
                float acc = 0.f;
                #pragma unroll
                for (int mm = 0; mm < 8; mm++) {
                    const int t = (mm * u) & 7;
                    acc += C8[t] * Q[mm].x - S8[t] * Q[mm].y;
                }
                orow[j + 64 * u] = xv[u] + acc * SCALE;
            }
        }
        BARG();
    }
}

// ---------------- launcher ------------------------------------------------------
extern "C" void kernel_launch(void* const* d_in, const int* in_sizes, int n_in,
                              void* d_out, int out_size) {
    const float* x = nullptr; const float* dt = nullptr;
    const float* cw = nullptr; const float* cb = nullptr;
    for (int i = 0; i < n_in; i++) {
        int s = in_sizes[i];
        if      (s == BATCH * CH * HH * WW) x  = (const float*)d_in[i];
        else if (s == BATCH)                dt = (const float*)d_in[i];
        else if (s == 64 * 64)              cw = (const float*)d_in[i];
        else if (s == 64)                   cb = (const float*)d_in[i];
    }
    float* out = (float*)d_out;

    cudaFuncSetAttribute(k_main, cudaFuncAttributeMaxDynamicSharedMemorySize,
                         SMEM_BYTES);
    cudaFuncSetAttribute(k_filt, cudaFuncAttributeMaxDynamicSharedMemorySize,
                         FILT_SMEM);

    k_tw  <<<1, 512>>>();
    k_filt<<<BATCH * 32, 512, FILT_SMEM>>>(x, cw, cb, dt);
    k_main<<<BATCH * CH, 1024, SMEM_BYTES>>>(x, out);
}

// round 15
// speedup vs baseline: 5.8893x; 1.0805x over previous
#include <cuda_runtime.h>
#include <math.h>

#define BATCH 8
#define CH    64
#define HH    256
#define WW    512
#define KF    64

// ---------------- device globals ----------------------------------------------
__device__ float2 g_filtm1[BATCH * KF * HH];          // (filt-1), [b][k][h]

// ---------------- helpers ------------------------------------------------------
__device__ __forceinline__ float2 cmulf2(float2 a, float2 b) {
    return make_float2(a.x * b.x - a.y * b.y, a.x * b.y + a.y * b.x);
}
__device__ __forceinline__ float2 cmulcf2(float2 a, float2 b) {   // a * conj(b)
    return make_float2(a.x * b.x + a.y * b.y, a.y * b.x - a.x * b.y);
}
__device__ __forceinline__ float2 cadd(float2 a, float2 b){return make_float2(a.x+b.x, a.y+b.y);}
__device__ __forceinline__ float2 csub(float2 a, float2 b){return make_float2(a.x-b.x, a.y-b.y);}
__device__ __forceinline__ float2 cmuli(float2 a, float s){ return make_float2(-s*a.y, s*a.x); }
// bank-conflict swizzle for S-row element indices (permutation of [0,256))
__device__ __forceinline__ int sw(int i){ return i ^ ((i & 0x30) >> 2); }

// 8-point DFT in registers. F=1: kernel e^{-2pi i tj/8}. F=-1: conj kernel.
template<int F>
__device__ __forceinline__ void dft8(float2* z) {
    const float r = 0.70710678118654752f;
    float2 a  = cadd(z[0], z[4]), b  = csub(z[0], z[4]);
    float2 c  = cadd(z[2], z[6]), d  = csub(z[2], z[6]);
    float2 E0 = cadd(a, c), E2 = csub(a, c);
    float2 di = cmuli(d, (float)(-F));
    float2 E1 = cadd(b, di), E3 = csub(b, di);
    float2 a2 = cadd(z[1], z[5]), b2 = csub(z[1], z[5]);
    float2 c2 = cadd(z[3], z[7]), d2 = csub(z[3], z[7]);
    float2 O0 = cadd(a2, c2), O2 = csub(a2, c2);
    float2 d2i = cmuli(d2, (float)(-F));
    float2 O1 = cadd(b2, d2i), O3 = csub(b2, d2i);
    float2 T1 = make_float2(r * (O1.x + F * O1.y), r * (O1.y - F * O1.x));
    float2 T2 = cmuli(O2, (float)(-F));
    float2 T3 = make_float2(r * (-O3.x + F * O3.y), r * (-O3.y - F * O3.x));
    z[0] = cadd(E0, O0); z[4] = csub(E0, O0);
    z[1] = cadd(E1, T1); z[5] = csub(E1, T1);
    z[2] = cadd(E2, T2); z[6] = csub(E2, T2);
    z[3] = cadd(E3, T3); z[7] = csub(E3, T3);
}

// ---------------- fused pool + filt: one block = (b, h) ------------------------
// 128 threads, small smem, 2048 CTAs -> deep latency hiding for the x stream.
__global__ void __launch_bounds__(128)
k_filt(const float* __restrict__ x,
       const float* __restrict__ conv_w,
       const float* __restrict__ conv_b,
       const float* __restrict__ dt) {
    __shared__ float Wm[4096];
    __shared__ float P[4096];      // P[c*64 + wf]
    __shared__ float bs[64];
    __shared__ float pr[64], pi[64];

    int tid = threadIdx.x;
    int b   = blockIdx.x >> 8;
    int h   = blockIdx.x & 255;

    for (int i = tid; i < 4096; i += 128) Wm[i] = conv_w[i];
    if (tid < 64) bs[tid] = conv_b[tid];

    const float4* xb = (const float4*)(x + ((size_t)(b * 64) * 256 + h) * 512);
    for (int idx = tid; idx < 4096; idx += 128) {
        int c = idx >> 6, wf = idx & 63;
        float4 a0 = xb[c * 32768 + wf * 2];
        float4 a1 = xb[c * 32768 + wf * 2 + 1];
        P[idx] = (a0.x + a0.y + a0.z + a0.w + a1.x + a1.y + a1.z + a1.w) * 0.125f;
    }
    __syncthreads();

    int wf   = tid & 63;
    int half = tid >> 6;
    float dtb = dt[b];
    float fre = 0.f, fim = 0.f;
    const float PIF = 3.14159265358979323846f;
    for (int r = half * 16; r < half * 16 + 16; r++) {
        float p1 = bs[r], p2 = bs[r + 32];
        const float* w1 = &Wm[r * 64];
        const float* w2 = &Wm[(r + 32) * 64];
        #pragma unroll 8
        for (int c = 0; c < 64; c++) {
            float pv = P[c * 64 + wf];
            p1 += w1[c] * pv;
            p2 += w2[c] * pv;
        }
        float e   = __expf(p1);
        float dcy = exp2f(-dtb * __log2f(1.f + e));      // (1+e^p1)^(-dt)
        float e2  = __expf(2.f * p2);
        float th  = __fdividef(e2 - 1.f, e2 + 1.f) * PIF;
        float sa, ca;
        __sincosf(th * dtb, &sa, &ca);
        fre += dcy * ca;
        fim += dcy * sa;
    }
    if (half == 1) { pr[wf] = fre; pi[wf] = fim; }
    __syncthreads();
    if (half == 0) {
        fre += pr[wf];
        fim += pi[wf];
        g_filtm1[(b * 64 + wf) * 256 + h] = make_float2(fre - 1.0f, fim);
    }
}

// ---------------- radix-4 Stockham 256-pt FFT (swizzled A, optional fused mul) --
template <bool INV, bool FUSE>
__device__ __forceinline__ void fft256_r4(float2* __restrict__ A,
                                          float2* __restrict__ B,
                                          const float2* __restrict__ TW,
                                          int lane,
                                          const float2* __restrict__ fg) {
    const float sgn = INV ? -1.0f : 1.0f;
    // ---- stage 0: A(swizzled) -> B
    #pragma unroll
    for (int t2 = 0; t2 < 2; t2++) {
        int p  = lane + 32 * t2;
        int sp = sw(p);
        float2 a = A[sp], b = A[sp + 64], c = A[sp + 128], d = A[sp + 192];
        float2 w1 = TW[p << 1];
        if (INV) w1.y = -w1.y;
        float2 w2 = cmulf2(w1, w1);
        float2 w3 = cmulf2(w2, w1);
        float2 apc = cadd(a, c), amc = csub(a, c);
        float2 bpd = cadd(b, d), bmd = csub(b, d);
        float2 y0 = cadd(apc, bpd);
        float2 y2 = cmulf2(w2, csub(apc, bpd));
        float2 y1 = cmulf2(w1, make_float2(amc.x + sgn * bmd.y, amc.y - sgn * bmd.x));
        float2 y3 = cmulf2(w3, make_float2(amc.x - sgn * bmd.y, amc.y + sgn * bmd.x));
        float4* dst4 = (float4*)(B + 4 * p);
        dst4[0] = make_float4(y0.x, y0.y, y1.x, y1.y);
        dst4[1] = make_float4(y2.x, y2.y, y3.x, y3.y);
    }
    __syncwarp();
    // ---- stage 1: B -> A(swizzled)
    #pragma unroll
    for (int t2 = 0; t2 < 2; t2++) {
        int t = lane + 32 * t2;
        int p = t >> 2, q = t & 3;
        float2 a = B[t], b = B[t + 64], c = B[t + 128], d = B[t + 192];
        float2 w1 = TW[p << 3];
        if (INV) w1.y = -w1.y;
        float2 w2 = cmulf2(w1, w1);
        float2 w3 = cmulf2(w2, w1);
        float2 apc = cadd(a, c), amc = csub(a, c);
        float2 bpd = cadd(b, d), bmd = csub(b, d);
        int base = q + 16 * p;
        int xb   = (p & 3) << 2;                 // swizzle bits for this base
        A[(base)      ^ xb] = cadd(apc, bpd);
        A[(base + 4)  ^ xb] = cmulf2(w1, make_float2(amc.x + sgn * bmd.y, amc.y - sgn * bmd.x));
        A[(base + 8)  ^ xb] = cmulf2(w2, csub(apc, bpd));
        A[(base + 12) ^ xb] = cmulf2(w3, make_float2(amc.x - sgn * bmd.y, amc.y + sgn * bmd.x));
    }
    __syncwarp();
    // ---- stage 2: A(swizzled) -> B
    #pragma unroll
    for (int t2 = 0; t2 < 2; t2++) {
        int t  = lane + 32 * t2;
        int st = sw(t);
        int p = t >> 4, q = t & 15;
        float2 a = A[st], b = A[st + 64], c = A[st + 128], d = A[st + 192];
        float2 w1 = TW[p << 5];
        if (INV) w1.y = -w1.y;
        float2 w2 = cmulf2(w1, w1);
        float2 w3 = cmulf2(w2, w1);
        float2 apc = cadd(a, c), amc = csub(a, c);
        float2 bpd = cadd(b, d), bmd = csub(b, d);
        int base = q + 64 * p;
        B[base]      = cadd(apc, bpd);
        B[base + 16] = cmulf2(w1, make_float2(amc.x + sgn * bmd.y, amc.y - sgn * bmd.x));
        B[base + 32] = cmulf2(w2, csub(apc, bpd));
        B[base + 48] = cmulf2(w3, make_float2(amc.x - sgn * bmd.y, amc.y + sgn * bmd.x));
    }
    __syncwarp();
    // ---- stage 3: B -> A(swizzled), optional fused filter multiply
    #pragma unroll
    for (int t2 = 0; t2 < 2; t2++) {
        int q  = lane + 32 * t2;
        int sq = sw(q);
        float2 a = B[q], b = B[q + 64], c = B[q + 128], d = B[q + 192];
        float2 apc = cadd(a, c), amc = csub(a, c);
        float2 bpd = cadd(b, d), bmd = csub(b, d);
        float2 y0 = cadd(apc, bpd);
        float2 y1 = make_float2(amc.x + sgn * bmd.y, amc.y - sgn * bmd.x);
        float2 y2 = csub(apc, bpd);
        float2 y3 = make_float2(amc.x - sgn * bmd.y, amc.y + sgn * bmd.x);
        if (FUSE) {
            y0 = cmulf2(y0, __ldg(&fg[q]));
            y1 = cmulf2(y1, __ldg(&fg[q + 64]));
            y2 = cmulf2(y2, __ldg(&fg[q + 128]));
            y3 = cmulf2(y3, __ldg(&fg[q + 192]));
        }
        A[sq]       = y0;
        A[sq + 64]  = y1;
        A[sq + 128] = y2;
        A[sq + 192] = y3;
    }
    __syncwarp();
}

// ---------------- fused main kernel: 1024 threads, 16 row-groups ----------------
#define S_STRIDE 257
#define G_STRIDE 68
#define GRP_PER  (8 * G_STRIDE)                   // 544 float2 per 64-thread group
#define NGRP 16
#define SMEM_BYTES ((64 * S_STRIDE + 512 + NGRP * GRP_PER) * 8)

// per-group named barrier: ids 1..15 (groups 14,15 share id 15, count 128).
// id 0 reserved for __syncthreads at phase transitions (never concurrent).
#define BARG() asm volatile("bar.sync %0, %1;" :: "r"(bar_id), "r"(bar_cnt) : "memory")

__global__ void __launch_bounds__(1024, 1)
k_main(const float* __restrict__ x, float* __restrict__ out) {
    extern __shared__ char smem_raw[];
    float2* S   = (float2*)smem_raw;            // [64][257] tile X[k][sw(h)]
    float2* TW  = S + 64 * S_STRIDE;            // 512 twiddles
    float2* GRP = TW + 512;                     // 16 groups x 544

    int tid  = threadIdx.x;
    int bc   = blockIdx.x;
    int b    = bc >> 6;
    const float* xim = x   + (size_t)bc * (HH * WW);
    float*       oim = out + (size_t)bc * (HH * WW);

    if (tid < 512) {
        float s, c;
        sincospif((float)tid / 256.0f, &s, &c);
        TW[tid] = make_float2(c, -s);
    }
    __syncthreads();

    int pair = tid >> 6;        // 0..15 group id
    int t64  = tid & 63;
    int bar_id  = (pair < 15) ? (pair + 1) : 15;
    int bar_cnt = (pair >= 14) ? 128 : 64;
    float2* grp = GRP + pair * GRP_PER;
    int m8  = t64 >> 3;
    int j08 = t64 & 7;

    // ================= Phase A: partial forward W-DFT (512 -> 64 bins) ========
    float v[8];
    {
        const float* row0 = xim + pair * 512;
        #pragma unroll
        for (int u = 0; u < 8; u++) v[u] = row0[t64 + 64 * u];
    }
    for (int it = 0; it < 16; it++) {
        int h  = it * 16 + pair;
        int hs = sw(h & 255) + 0;   // h < 256 always
        hs = sw(h);
        // ---- step1: real DFT8 across the 8 blocks (j = t64)
        {
            int j = t64;
            float e0 = v[0] + v[4], e1 = v[1] + v[5], e2 = v[2] + v[6], e3 = v[3] + v[7];
            float o0 = v[0] - v[4], o1 = v[1] - v[5], o2 = v[2] - v[6], o3 = v[3] - v[7];
            float s02 = e0 + e2, s13 = e1 + e3, d02 = e0 - e2, d13 = e1 - e3;
            const float R = 0.70710678118654752f;
            float t1 = R * (o1 - o3), t2 = R * (o1 + o3);
            grp[0 * G_STRIDE + j] = make_float2(s02 + s13, 0.f);
            grp[4 * G_STRIDE + j] = make_float2(s02 - s13, 0.f);
            grp[2 * G_STRIDE + j] = make_float2(d02, -d13);
            grp[6 * G_STRIDE + j] = make_float2(d02,  d13);
            grp[1 * G_STRIDE + j] = make_float2(o0 + t1, -o2 - t2);
            grp[3 * G_STRIDE + j] = make_float2(o0 - t1,  o2 - t2);
            grp[5 * G_STRIDE + j] = make_float2(o0 - t1, -(o2 - t2));
            grp[7 * G_STRIDE + j] = make_float2(o0 + t1,  o2 + t2);
        }
        BARG();
        // prefetch next row
        if (it < 15) {
            const float* nr = xim + (h + 16) * 512;
            #pragma unroll
            for (int u = 0; u < 8; u++) v[u] = nr[t64 + 64 * u];
        }
        // ---- pass1: each thread reads/writes ONLY its own mod-8 slot class ->
        //      no cross-thread hazard between read and write (no barrier).
        {
            float2 wm = TW[8 * m8];
            float2 w  = make_float2(1.f, 0.f);
            float2 z[8];
            #pragma unroll
            for (int j1 = 0; j1 < 8; j1++) {
                float2 g = grp[m8 * G_STRIDE + j08 + 8 * j1];
                z[j1] = cmulf2(g, w);
                w = cmulf2(w, wm);
            }
            dft8<1>(z);
            #pragma unroll
            for (int t = 0; t < 8; t++)
                grp[m8 * G_STRIDE + t * 8 + j08] = z[t];
        }
        BARG();
        // ---- pass2: X[k] = sum_{j0} W512^{k j0} P[k&7][j0][k>>3]
        {
            int k = t64, mm = k & 7, tt = k >> 3;
            const float4* pp = (const float4*)(grp + mm * G_STRIDE + tt * 8);
            float2 wk = TW[k];
            float2 w  = make_float2(1.f, 0.f);
            float2 acc = make_float2(0.f, 0.f);
            #pragma unroll
            for (int q = 0; q < 4; q++) {
                float4 g2 = pp[q];
                acc.x += w.x * g2.x - w.y * g2.y;
                acc.y += w.x * g2.y + w.y * g2.x;
                w = cmulf2(w, wk);
                acc.x += w.x * g2.z - w.y * g2.w;
                acc.y += w.x * g2.w + w.y * g2.z;
                w = cmulf2(w, wk);
            }
            S[k * S_STRIDE + hs] = acc;
        }
        BARG();
    }
    __syncthreads();

    // ================= Phase B: FFT_H, multiply (fused), IFFT_H ===============
    {
        int wid  = tid >> 5;                // 0..31
        int lane = tid & 31;
        float2* scr = GRP + wid * 272;      // 32 warps x 272 = 8704 = 16*544
        for (int k = wid; k < 64; k += 32) {
            float2* row = S + k * S_STRIDE;
            const float2* fg = &g_filtm1[(b * 64 + k) * 256];
            fft256_r4<false, true >(row, scr, TW, lane, fg);
            fft256_r4<true,  false>(row, scr, TW, lane, nullptr);
        }
    }
    __syncthreads();

    // ================= Phase C: partial inverse W-DFT, out = x + delta ========
    const float SCALE = 2.0f / (256.0f * 512.0f);
    const float RT = 0.70710678118654752f;
    const float C8[8] = {1.f,  RT, 0.f, -RT, -1.f, -RT, 0.f,  RT};
    const float S8[8] = {0.f,  RT, 1.f,  RT,  0.f, -RT, -1.f, -RT};
    for (int it = 0; it < 16; it++) {
        int h  = it * 16 + pair;
        int hs = sw(h);
        const float* rowx = xim + h * 512;
        float xv[8];
        #pragma unroll
        for (int u = 0; u < 8; u++) xv[u] = rowx[t64 + 64 * u];
        // ---- pass1
        {
            float2 ws = TW[8 * j08];
            float2 w  = make_float2(1.f, 0.f);
            float2 z[8];
            #pragma unroll
            for (int a = 0; a < 8; a++) {
                float2 zz = S[(8 * a + m8) * S_STRIDE + hs];
                z[a] = cmulcf2(zz, w);
                w = cmulf2(w, ws);
            }
            if (m8 == 0) { z[0].x *= 0.5f; z[0].y *= 0.5f; }
            dft8<-1>(z);
            float2 wq  = TW[(m8 * j08) & 511];
            float2 wqs = TW[8 * m8];
            #pragma unroll
            for (int j1 = 0; j1 < 8; j1++) {
                grp[m8 * G_STRIDE + j08 + 8 * j1] = cmulcf2(z[j1], wq);
                wq = cmulf2(wq, wqs);
            }
        }
        BARG();
        // ---- output: delta[j+64u] = Re( sum_m W8^{-mu} Q_m[j] )
        {
            int j = t64;
            float2 Q[8];
            #pragma unroll
            for (int mm = 0; mm < 8; mm++) Q[mm] = grp[mm * G_STRIDE + j];
            float* orow = oim + h * 512;
            #pragma unroll
            for (int u = 0; u < 8; u++) {
                float acc = 0.f;
                #pragma unroll
                for (int mm = 0; mm < 8; mm++) {
                    const int t = (mm * u) & 7;
                    acc += C8[t] * Q[mm].x - S8[t] * Q[mm].y;
                }
                orow[j + 64 * u] = xv[u] + acc * SCALE;
            }
        }
        BARG();
    }
}

// ---------------- launcher ------------------------------------------------------
extern "C" void kernel_launch(void* const* d_in, const int* in_sizes, int n_in,
                              void* d_out, int out_size) {
    const float* x = nullptr; const float* dt = nullptr;
    const float* cw = nullptr; const float* cb = nullptr;
    for (int i = 0; i < n_in; i++) {
        int s = in_sizes[i];
        if      (s == BATCH * CH * HH * WW) x  = (const float*)d_in[i];
        else if (s == BATCH)                dt = (const float*)d_in[i];
        else if (s == 64 * 64)              cw = (const float*)d_in[i];
        else if (s == 64)                   cb = (const float*)d_in[i];
    }
    float* out = (float*)d_out;

    cudaFuncSetAttribute(k_main, cudaFuncAttributeMaxDynamicSharedMemorySize,
                         SMEM_BYTES);

    k_filt<<<BATCH * 256, 128>>>(x, cw, cb, dt);
    k_main<<<BATCH * CH, 1024, SMEM_BYTES>>>(x, out);
}

// round 16
// speedup vs baseline: 6.1981x; 1.0524x over previous
#include <cuda_runtime.h>
#include <math.h>

#define BATCH 8
#define CH    64
#define HH    256
#define WW    512

// ---------------- device globals ----------------------------------------------
__device__ float2 g_filtm1[BATCH * 64 * HH];          // (filt-1), [b][k][h]

// ---------------- helpers ------------------------------------------------------
__device__ __forceinline__ float2 cmulf2(float2 a, float2 b) {
    return make_float2(a.x * b.x - a.y * b.y, a.x * b.y + a.y * b.x);
}
__device__ __forceinline__ float2 cmulcf2(float2 a, float2 b) {   // a * conj(b)
    return make_float2(a.x * b.x + a.y * b.y, a.y * b.x - a.x * b.y);
}
__device__ __forceinline__ float2 cadd(float2 a, float2 b){return make_float2(a.x+b.x, a.y+b.y);}
__device__ __forceinline__ float2 csub(float2 a, float2 b){return make_float2(a.x-b.x, a.y-b.y);}
__device__ __forceinline__ float2 cmuli(float2 a, float s){ return make_float2(-s*a.y, s*a.x); }
// bank-conflict swizzle for S-row element indices (permutation of [0,256))
__device__ __forceinline__ int sw(int i){ return i ^ ((i & 0x30) >> 2); }

// 8-point DFT in registers. F=1: kernel e^{-2pi i tj/8}. F=-1: conj kernel.
template<int F>
__device__ __forceinline__ void dft8(float2* z) {
    const float r = 0.70710678118654752f;
    float2 a  = cadd(z[0], z[4]), b  = csub(z[0], z[4]);
    float2 c  = cadd(z[2], z[6]), d  = csub(z[2], z[6]);
    float2 E0 = cadd(a, c), E2 = csub(a, c);
    float2 di = cmuli(d, (float)(-F));
    float2 E1 = cadd(b, di), E3 = csub(b, di);
    float2 a2 = cadd(z[1], z[5]), b2 = csub(z[1], z[5]);
    float2 c2 = cadd(z[3], z[7]), d2 = csub(z[3], z[7]);
    float2 O0 = cadd(a2, c2), O2 = csub(a2, c2);
    float2 d2i = cmuli(d2, (float)(-F));
    float2 O1 = cadd(b2, d2i), O3 = csub(b2, d2i);
    float2 T1 = make_float2(r * (O1.x + F * O1.y), r * (O1.y - F * O1.x));
    float2 T2 = cmuli(O2, (float)(-F));
    float2 T3 = make_float2(r * (-O3.x + F * O3.y), r * (-O3.y - F * O3.x));
    z[0] = cadd(E0, O0); z[4] = csub(E0, O0);
    z[1] = cadd(E1, T1); z[5] = csub(E1, T1);
    z[2] = cadd(E2, T2); z[6] = csub(E2, T2);
    z[3] = cadd(E3, T3); z[7] = csub(E3, T3);
}

// ---------------- fused pool + filt: one block = (b, h) ------------------------
__global__ void __launch_bounds__(128)
k_filt(const float* __restrict__ x,
       const float* __restrict__ conv_w,
       const float* __restrict__ conv_b,
       const float* __restrict__ dt) {
    __shared__ float WmT[64 * 68];   // [c][r], padded stride 68
    __shared__ float P[4096];        // P[c*64 + wf]
    __shared__ float bs[64];
    __shared__ float pr[64], pi[64];

    int tid = threadIdx.x;
    int b   = blockIdx.x >> 8;
    int h   = blockIdx.x & 255;

    // transpose conv_w into WmT[c*68 + r]
    for (int i = tid; i < 4096; i += 128) {
        int r = i >> 6, c = i & 63;
        WmT[c * 68 + r] = conv_w[i];
    }
    if (tid < 64) bs[tid] = conv_b[tid];

    const float4* xb = (const float4*)(x + ((size_t)(b * 64) * 256 + h) * 512);
    #pragma unroll 4
    for (int idx = tid; idx < 4096; idx += 128) {
        int c = idx >> 6, wf = idx & 63;
        float4 a0 = xb[c * 32768 + wf * 2];
        float4 a1 = xb[c * 32768 + wf * 2 + 1];
        P[idx] = (a0.x + a0.y + a0.z + a0.w + a1.x + a1.y + a1.z + a1.w) * 0.125f;
    }
    __syncthreads();

    int wf    = tid & 63;
    int half  = tid >> 6;
    int rbase = half * 16;
    float acc1[16], acc2[16];
    #pragma unroll
    for (int u = 0; u < 16; u++) { acc1[u] = 0.f; acc2[u] = 0.f; }

    for (int c = 0; c < 64; c++) {
        float pv = P[c * 64 + wf];
        const float4* w1p = (const float4*)&WmT[c * 68 + rbase];
        const float4* w2p = (const float4*)&WmT[c * 68 + 32 + rbase];
        #pragma unroll
        for (int q = 0; q < 4; q++) {
            float4 w1 = w1p[q], w2 = w2p[q];
            acc1[4*q+0] += w1.x * pv; acc1[4*q+1] += w1.y * pv;
            acc1[4*q+2] += w1.z * pv; acc1[4*q+3] += w1.w * pv;
            acc2[4*q+0] += w2.x * pv; acc2[4*q+1] += w2.y * pv;
            acc2[4*q+2] += w2.z * pv; acc2[4*q+3] += w2.w * pv;
        }
    }

    float dtb = dt[b];
    float fre = 0.f, fim = 0.f;
    const float PIF = 3.14159265358979323846f;
    #pragma unroll 4
    for (int u = 0; u < 16; u++) {
        int r = rbase + u;
        float p1 = acc1[u] + bs[r];
        float p2 = acc2[u] + bs[r + 32];
        float e   = __expf(p1);
        float dcy = exp2f(-dtb * __log2f(1.f + e));      // (1+e^p1)^(-dt)
        float e2  = __expf(2.f * p2);
        float th  = __fdividef(e2 - 1.f, e2 + 1.f) * PIF;
        float sa, ca;
        __sincosf(th * dtb, &sa, &ca);
        fre += dcy * ca;
        fim += dcy * sa;
    }
    if (half == 1) { pr[wf] = fre; pi[wf] = fim; }
    __syncthreads();
    if (half == 0) {
        fre += pr[wf];
        fim += pi[wf];
        g_filtm1[(b * 64 + wf) * 256 + h] = make_float2(fre - 1.0f, fim);
    }
}

// ---------------- fused forward FFT256 + filter + inverse FFT256 ---------------
// A = S row (swizzled element order), B = per-warp scratch (256 float2).
__device__ __forceinline__ void fft256_roundtrip(float2* __restrict__ A,
                                                 float2* __restrict__ B,
                                                 const float2* __restrict__ TW,
                                                 int lane,
                                                 const float2* __restrict__ fg) {
    // ---- FWD stage 0: A(sw) -> B
    #pragma unroll
    for (int t2 = 0; t2 < 2; t2++) {
        int p  = lane + 32 * t2;
        int sp = sw(p);
        float2 a = A[sp], b = A[sp + 64], c = A[sp + 128], d = A[sp + 192];
        float2 w1 = TW[p << 1];
        float2 w2 = cmulf2(w1, w1);
        float2 w3 = cmulf2(w2, w1);
        float2 apc = cadd(a, c), amc = csub(a, c);
        float2 bpd = cadd(b, d), bmd = csub(b, d);
        float2 y0 = cadd(apc, bpd);
        float2 y2 = cmulf2(w2, csub(apc, bpd));
        float2 y1 = cmulf2(w1, make_float2(amc.x + bmd.y, amc.y - bmd.x));
        float2 y3 = cmulf2(w3, make_float2(amc.x - bmd.y, amc.y + bmd.x));
        float4* dst4 = (float4*)(B + 4 * p);
        dst4[0] = make_float4(y0.x, y0.y, y1.x, y1.y);
        dst4[1] = make_float4(y2.x, y2.y, y3.x, y3.y);
    }
    __syncwarp();
    // ---- FWD stage 1: B -> A(sw)
    #pragma unroll
    for (int t2 = 0; t2 < 2; t2++) {
        int t = lane + 32 * t2;
        int p = t >> 2, q = t & 3;
        float2 a = B[t], b = B[t + 64], c = B[t + 128], d = B[t + 192];
        float2 w1 = TW[p << 3];
        float2 w2 = cmulf2(w1, w1);
        float2 w3 = cmulf2(w2, w1);
        float2 apc = cadd(a, c), amc = csub(a, c);
        float2 bpd = cadd(b, d), bmd = csub(b, d);
        int base = q + 16 * p;
        int xb   = (p & 3) << 2;
        A[(base)      ^ xb] = cadd(apc, bpd);
        A[(base + 4)  ^ xb] = cmulf2(w1, make_float2(amc.x + bmd.y, amc.y - bmd.x));
        A[(base + 8)  ^ xb] = cmulf2(w2, csub(apc, bpd));
        A[(base + 12) ^ xb] = cmulf2(w3, make_float2(amc.x - bmd.y, amc.y + bmd.x));
    }
    __syncwarp();
    // ---- FWD stage 2: A(sw) -> B
    #pragma unroll
    for (int t2 = 0; t2 < 2; t2++) {
        int t  = lane + 32 * t2;
        int st = sw(t);
        int p = t >> 4, q = t & 15;
        float2 a = A[st], b = A[st + 64], c = A[st + 128], d = A[st + 192];
        float2 w1 = TW[p << 5];
        float2 w2 = cmulf2(w1, w1);
        float2 w3 = cmulf2(w2, w1);
        float2 apc = cadd(a, c), amc = csub(a, c);
        float2 bpd = cadd(b, d), bmd = csub(b, d);
        int base = q + 64 * p;
        B[base]      = cadd(apc, bpd);
        B[base + 16] = cmulf2(w1, make_float2(amc.x + bmd.y, amc.y - bmd.x));
        B[base + 32] = cmulf2(w2, csub(apc, bpd));
        B[base + 48] = cmulf2(w3, make_float2(amc.x - bmd.y, amc.y + bmd.x));
    }
    __syncwarp();
    // ---- FUSED: FWD stage 3 + filter + INV stage 0, all in registers: B -> B
    {
        float2 rr[8];
        #pragma unroll
        for (int t2 = 0; t2 < 2; t2++) {
            int q = lane + 32 * t2;
            rr[4*t2+0] = B[q];       rr[4*t2+1] = B[q + 64];
            rr[4*t2+2] = B[q + 128]; rr[4*t2+3] = B[q + 192];
        }
        #pragma unroll
        for (int t2 = 0; t2 < 2; t2++) {
            int q = lane + 32 * t2;
            // filter loads issued early
            float2 f0 = __ldg(&fg[q]),       f1 = __ldg(&fg[q + 64]);
            float2 f2 = __ldg(&fg[q + 128]), f3 = __ldg(&fg[q + 192]);
            float2 a = rr[4*t2+0], b = rr[4*t2+1], c = rr[4*t2+2], d = rr[4*t2+3];
            // forward stage3 (no twiddle)
            float2 apc = cadd(a, c), amc = csub(a, c);
            float2 bpd = cadd(b, d), bmd = csub(b, d);
            float2 y0 = cadd(apc, bpd);
            float2 y1 = make_float2(amc.x + bmd.y, amc.y - bmd.x);
            float2 y2 = csub(apc, bpd);
            float2 y3 = make_float2(amc.x - bmd.y, amc.y + bmd.x);
            // filter
            y0 = cmulf2(y0, f0); y1 = cmulf2(y1, f1);
            y2 = cmulf2(y2, f2); y3 = cmulf2(y3, f3);
            // inverse stage0 (conj twiddles, sgn = -1)
            float2 w1 = TW[q << 1]; w1.y = -w1.y;
            float2 w2 = cmulf2(w1, w1);
            float2 w3 = cmulf2(w2, w1);
            apc = cadd(y0, y2); amc = csub(y0, y2);
            bpd = cadd(y1, y3); bmd = csub(y1, y3);
            float2 z0 = cadd(apc, bpd);
            float2 z2 = cmulf2(w2, csub(apc, bpd));
            float2 z1 = cmulf2(w1, make_float2(amc.x - bmd.y, amc.y + bmd.x));
            float2 z3 = cmulf2(w3, make_float2(amc.x + bmd.y, amc.y - bmd.x));
            float4* dst4 = (float4*)(B + 4 * q);
            dst4[0] = make_float4(z0.x, z0.y, z1.x, z1.y);
            dst4[1] = make_float4(z2.x, z2.y, z3.x, z3.y);
        }
    }
    __syncwarp();
    // ---- INV stage 1: B -> A(sw)
    #pragma unroll
    for (int t2 = 0; t2 < 2; t2++) {
        int t = lane + 32 * t2;
        int p = t >> 2, q = t & 3;
        float2 a = B[t], b = B[t + 64], c = B[t + 128], d = B[t + 192];
        float2 w1 = TW[p << 3]; w1.y = -w1.y;
        float2 w2 = cmulf2(w1, w1);
        float2 w3 = cmulf2(w2, w1);
        float2 apc = cadd(a, c), amc = csub(a, c);
        float2 bpd = cadd(b, d), bmd = csub(b, d);
        int base = q + 16 * p;
        int xb   = (p & 3) << 2;
        A[(base)      ^ xb] = cadd(apc, bpd);
        A[(base + 4)  ^ xb] = cmulf2(w1, make_float2(amc.x - bmd.y, amc.y + bmd.x));
        A[(base + 8)  ^ xb] = cmulf2(w2, csub(apc, bpd));
        A[(base + 12) ^ xb] = cmulf2(w3, make_float2(amc.x + bmd.y, amc.y - bmd.x));
    }
    __syncwarp();
    // ---- INV stage 2: A(sw) -> B
    #pragma unroll
    for (int t2 = 0; t2 < 2; t2++) {
        int t  = lane + 32 * t2;
        int st = sw(t);
        int p = t >> 4, q = t & 15;
        float2 a = A[st], b = A[st + 64], c = A[st + 128], d = A[st + 192];
        float2 w1 = TW[p << 5]; w1.y = -w1.y;
        float2 w2 = cmulf2(w1, w1);
        float2 w3 = cmulf2(w2, w1);
        float2 apc = cadd(a, c), amc = csub(a, c);
        float2 bpd = cadd(b, d), bmd = csub(b, d);
        int base = q + 64 * p;
        B[base]      = cadd(apc, bpd);
        B[base + 16] = cmulf2(w1, make_float2(amc.x - bmd.y, amc.y + bmd.x));
        B[base + 32] = cmulf2(w2, csub(apc, bpd));
        B[base + 48] = cmulf2(w3, make_float2(amc.x + bmd.y, amc.y - bmd.x));
    }
    __syncwarp();
    // ---- INV stage 3: B -> A(sw), no twiddle
    #pragma unroll
    for (int t2 = 0; t2 < 2; t2++) {
        int q  = lane + 32 * t2;
        int sq = sw(q);
        float2 a = B[q], b = B[q + 64], c = B[q + 128], d = B[q + 192];
        float2 apc = cadd(a, c), amc = csub(a, c);
        float2 bpd = cadd(b, d), bmd = csub(b, d);
        A[sq]       = cadd(apc, bpd);
        A[sq + 64]  = make_float2(amc.x - bmd.y, amc.y + bmd.x);
        A[sq + 128] = csub(apc, bpd);
        A[sq + 192] = make_float2(amc.x + bmd.y, amc.y - bmd.x);
    }
    __syncwarp();
}

// ---------------- fused main kernel: 1024 threads, 16 row-groups ----------------
#define S_STRIDE 257
#define G_STRIDE 68
#define GRP_PER  (8 * G_STRIDE)                   // 544 float2 per 64-thread group
#define NGRP 16
#define SMEM_BYTES ((64 * S_STRIDE + 512 + NGRP * GRP_PER) * 8)

#define BARG() asm volatile("bar.sync %0, %1;" :: "r"(bar_id), "r"(bar_cnt) : "memory")

__global__ void __launch_bounds__(1024, 1)
k_main(const float* __restrict__ x, float* __restrict__ out) {
    extern __shared__ char smem_raw[];
    float2* S   = (float2*)smem_raw;            // [64][257] tile X[k][sw(h)]
    float2* TW  = S + 64 * S_STRIDE;            // 512 twiddles
    float2* GRP = TW + 512;                     // 16 groups x 544

    int tid  = threadIdx.x;
    int bc   = blockIdx.x;
    int b    = bc >> 6;
    const float* xim = x   + (size_t)bc * (HH * WW);
    float*       oim = out + (size_t)bc * (HH * WW);

    if (tid < 512) {
        float s, c;
        sincospif((float)tid / 256.0f, &s, &c);
        TW[tid] = make_float2(c, -s);
    }
    __syncthreads();

    int pair = tid >> 6;        // 0..15 group id
    int t64  = tid & 63;
    int bar_id  = (pair < 15) ? (pair + 1) : 15;
    int bar_cnt = (pair >= 14) ? 128 : 64;
    float2* grp = GRP + pair * GRP_PER;
    int m8  = t64 >> 3;
    int j08 = t64 & 7;
    int rowm = (m8 == 0 || m8 == 4) ? 0 : ((m8 < 4) ? m8 : 8 - m8);

    // ================= Phase A: partial forward W-DFT (512 -> 64 bins) ========
    float v[8];
    {
        const float* row0 = xim + pair * 512;
        #pragma unroll
        for (int u = 0; u < 8; u++) v[u] = row0[t64 + 64 * u];
    }
    for (int it = 0; it < 16; it++) {
        int h  = it * 16 + pair;
        int hs = sw(h);
        // ---- step1: real DFT8, symmetric half only (G0,G4 packed; G1..G3)
        {
            int j = t64;
            float e0 = v[0] + v[4], e1 = v[1] + v[5], e2 = v[2] + v[6], e3 = v[3] + v[7];
            float o0 = v[0] - v[4], o1 = v[1] - v[5], o2 = v[2] - v[6], o3 = v[3] - v[7];
            float s02 = e0 + e2, s13 = e1 + e3, d02 = e0 - e2, d13 = e1 - e3;
            const float R = 0.70710678118654752f;
            float t1 = R * (o1 - o3), t2 = R * (o1 + o3);
            grp[0 * G_STRIDE + j] = make_float2(s02 + s13, s02 - s13);  // G0 | G4
            grp[1 * G_STRIDE + j] = make_float2(o0 + t1, -o2 - t2);     // G1
            grp[2 * G_STRIDE + j] = make_float2(d02, -d13);             // G2
            grp[3 * G_STRIDE + j] = make_float2(o0 - t1,  o2 - t2);     // G3
        }
        BARG();
        // prefetch next row
        if (it < 15) {
            const float* nr = xim + (h + 16) * 512;
            #pragma unroll
            for (int u = 0; u < 8; u++) v[u] = nr[t64 + 64 * u];
        }
        // ---- pass1: P[m][t][j0] = DFT8_{j1}( W64^{m j1} G[m][j0+8j1] )
        {
            float2 wm = TW[8 * m8];
            float2 w  = make_float2(1.f, 0.f);
            float2 z[8];
            #pragma unroll
            for (int j1 = 0; j1 < 8; j1++) {
                float2 raw = grp[rowm * G_STRIDE + j08 + 8 * j1];
                float2 g;
                if (m8 == 0)      g = make_float2(raw.x, 0.f);
                else if (m8 == 4) g = make_float2(raw.y, 0.f);
                else if (m8 < 4)  g = raw;
                else              g = make_float2(raw.x, -raw.y);
                z[j1] = cmulf2(g, w);
                w = cmulf2(w, wm);
            }
            dft8<1>(z);
            BARG();   // all G reads complete before P overwrites shared rows
            #pragma unroll
            for (int t = 0; t < 8; t++)
                grp[m8 * G_STRIDE + t * 8 + j08] = z[t];
        }
        BARG();
        // ---- pass2: X[k] = sum_{j0} W512^{k j0} P[k&7][k>>3][j0]
        {
            int k = t64, mm = k & 7, tt = k >> 3;
            const float4* pp = (const float4*)(grp + mm * G_STRIDE + tt * 8);
            float2 wk = TW[k];
            float2 w  = make_float2(1.f, 0.f);
            float2 acc = make_float2(0.f, 0.f);
            #pragma unroll
            for (int q = 0; q < 4; q++) {
                float4 g2 = pp[q];
                acc.x += w.x * g2.x - w.y * g2.y;
                acc.y += w.x * g2.y + w.y * g2.x;
                w = cmulf2(w, wk);
                acc.x += w.x * g2.z - w.y * g2.w;
                acc.y += w.x * g2.w + w.y * g2.z;
                w = cmulf2(w, wk);
            }
            S[k * S_STRIDE + hs] = acc;
        }
        BARG();
    }
    __syncthreads();

    // ================= Phase B: fused FFT / filter / IFFT along H =============
    {
        int wid  = tid >> 5;                // 0..31
        int lane = tid & 31;
        float2* scr = GRP + wid * 272;      // 32 warps x 272 = 8704 = 16*544
        for (int k = wid; k < 64; k += 32) {
            float2* row = S + k * S_STRIDE;
            const float2* fg = &g_filtm1[(b * 64 + k) * 256];
            fft256_roundtrip(row, scr, TW, lane, fg);
        }
    }
    __syncthreads();

    // ================= Phase C: partial inverse W-DFT, out = x + delta ========
    const float SCALE = 2.0f / (256.0f * 512.0f);
    const float RT = 0.70710678118654752f;
    const float C8[8] = {1.f,  RT, 0.f, -RT, -1.f, -RT, 0.f,  RT};
    const float S8[8] = {0.f,  RT, 1.f,  RT,  0.f, -RT, -1.f, -RT};
    for (int it = 0; it < 16; it++) {
        int h  = it * 16 + pair;
        int hs = sw(h);
        const float* rowx = xim + h * 512;
        float xv[8];
        #pragma unroll
        for (int u = 0; u < 8; u++) xv[u] = rowx[t64 + 64 * u];
        // ---- pass1: R = IDFT8_a( conj(W64^{a j0}) Z[8a+m] ); Q = conj(W512^{m j}) R
        {
            float2 ws = TW[8 * j08];
            float2 w  = make_float2(1.f, 0.f);
            float2 z[8];
            #pragma unroll
            for (int a = 0; a < 8; a++) {
                float2 zz = S[(8 * a + m8) * S_STRIDE + hs];
                z[a] = cmulcf2(zz, w);
                w = cmulf2(w, ws);
            }
            if (m8 == 0) { z[0].x *= 0.5f; z[0].y *= 0.5f; }
            dft8<-1>(z);
            float2 wq  = TW[(m8 * j08) & 511];
            float2 wqs = TW[8 * m8];
            #pragma unroll
            for (int j1 = 0; j1 < 8; j1++) {
                grp[m8 * G_STRIDE + j08 + 8 * j1] = cmulcf2(z[j1], wq);
                wq = cmulf2(wq, wqs);
            }
        }
        BARG();
        // ---- output: delta[j+64u] = Re( sum_m W8^{-mu} Q_m[j] )
        {
            int j = t64;
            float2 Q[8];
            #pragma unroll
            for (int mm = 0; mm < 8; mm++) Q[mm] = grp[mm * G_STRIDE + j];
            float* orow = oim + h * 512;
            #pragma unroll
            for (int u = 0; u < 8; u++) {
                float acc = 0.f;
                #pragma unroll
                for (int mm = 0; mm < 8; mm++) {
                    const int t = (mm * u) & 7;
                    acc += C8[t] * Q[mm].x - S8[t] * Q[mm].y;
                }
                orow[j + 64 * u] = xv[u] + acc * SCALE;
            }
        }
        BARG();
    }
}

// ---------------- launcher ------------------------------------------------------
extern "C" void kernel_launch(void* const* d_in, const int* in_sizes, int n_in,
                              void* d_out, int out_size) {
    const float* x = nullptr; const float* dt = nullptr;
    const float* cw = nullptr; const float* cb = nullptr;
    for (int i = 0; i < n_in; i++) {
        int s = in_sizes[i];
        if      (s == BATCH * CH * HH * WW) x  = (const float*)d_in[i];
        else if (s == BATCH)                dt = (const float*)d_in[i];
        else if (s == 64 * 64)              cw = (const float*)d_in[i];
        else if (s == 64)                   cb = (const float*)d_in[i];
    }
    float* out = (float*)d_out;

    cudaFuncSetAttribute(k_main, cudaFuncAttributeMaxDynamicSharedMemorySize,
                         SMEM_BYTES);

    k_filt<<<BATCH * 256, 128>>>(x, cw, cb, dt);
    k_main<<<BATCH * CH, 1024, SMEM_BYTES>>>(x, out);
}

// round 17
// speedup vs baseline: 6.4674x; 1.0434x over previous
#include <cuda_runtime.h>
#include <math.h>

#define BATCH 8
#define CH    64
#define HH    256
#define WW    512

// ---------------- device globals ----------------------------------------------
__device__ float2 g_filtm1[BATCH * 64 * HH];          // (filt-1), [b][k][h]

// ---------------- helpers ------------------------------------------------------
__device__ __forceinline__ float2 cmulf2(float2 a, float2 b) {
    return make_float2(a.x * b.x - a.y * b.y, a.x * b.y + a.y * b.x);
}
__device__ __forceinline__ float2 cmulcf2(float2 a, float2 b) {   // a * conj(b)
    return make_float2(a.x * b.x + a.y * b.y, a.y * b.x - a.x * b.y);
}
__device__ __forceinline__ float2 cadd(float2 a, float2 b){return make_float2(a.x+b.x, a.y+b.y);}
__device__ __forceinline__ float2 csub(float2 a, float2 b){return make_float2(a.x-b.x, a.y-b.y);}
__device__ __forceinline__ float2 cmuli(float2 a, float s){ return make_float2(-s*a.y, s*a.x); }
// bank-conflict swizzle for S-row element indices (permutation of [0,256))
__device__ __forceinline__ int sw(int i){ return i ^ ((i & 0x30) >> 2); }

// 8-point DFT in registers. F=1: kernel e^{-2pi i tj/8}. F=-1: conj kernel.
template<int F>
__device__ __forceinline__ void dft8(float2* z) {
    const float r = 0.70710678118654752f;
    float2 a  = cadd(z[0], z[4]), b  = csub(z[0], z[4]);
    float2 c  = cadd(z[2], z[6]), d  = csub(z[2], z[6]);
    float2 E0 = cadd(a, c), E2 = csub(a, c);
    float2 di = cmuli(d, (float)(-F));
    float2 E1 = cadd(b, di), E3 = csub(b, di);
    float2 a2 = cadd(z[1], z[5]), b2 = csub(z[1], z[5]);
    float2 c2 = cadd(z[3], z[7]), d2 = csub(z[3], z[7]);
    float2 O0 = cadd(a2, c2), O2 = csub(a2, c2);
    float2 d2i = cmuli(d2, (float)(-F));
    float2 O1 = cadd(b2, d2i), O3 = csub(b2, d2i);
    float2 T1 = make_float2(r * (O1.x + F * O1.y), r * (O1.y - F * O1.x));
    float2 T2 = cmuli(O2, (float)(-F));
    float2 T3 = make_float2(r * (-O3.x + F * O3.y), r * (-O3.y - F * O3.x));
    z[0] = cadd(E0, O0); z[4] = csub(E0, O0);
    z[1] = cadd(E1, T1); z[5] = csub(E1, T1);
    z[2] = cadd(E2, T2); z[6] = csub(E2, T2);
    z[3] = cadd(E3, T3); z[7] = csub(E3, T3);
}

// ---------------- fused pool + filt: one block = (b, h), 256 threads -----------
// 4-way split of the 32 rank rows; quarter q owns ranks [q*8, q*8+8).
__global__ void __launch_bounds__(256)
k_filt(const float* __restrict__ x,
       const float* __restrict__ conv_w,
       const float* __restrict__ conv_b,
       const float* __restrict__ dt) {
    __shared__ float WmT[64 * 68];   // [c][r], padded stride 68
    __shared__ float P[4096];        // P[c*64 + wf]
    __shared__ float bs[64];
    __shared__ float redr[4 * 64];
    __shared__ float redi[4 * 64];

    int tid = threadIdx.x;
    int b   = blockIdx.x >> 8;
    int h   = blockIdx.x & 255;

    // transpose conv_w into WmT[c*68 + r]
    for (int i = tid; i < 4096; i += 256) {
        int r = i >> 6, c = i & 63;
        WmT[c * 68 + r] = conv_w[i];
    }
    if (tid < 64) bs[tid] = conv_b[tid];

    // pool: P[c*64 + wf] = mean of 8 consecutive x values of row (b,c,h)
    const float4* xb = (const float4*)(x + ((size_t)(b * 64) * 256 + h) * 512);
    #pragma unroll 4
    for (int idx = tid; idx < 4096; idx += 256) {
        int c = idx >> 6, wf = idx & 63;
        float4 a0 = xb[c * 32768 + wf * 2];
        float4 a1 = xb[c * 32768 + wf * 2 + 1];
        P[idx] = (a0.x + a0.y + a0.z + a0.w + a1.x + a1.y + a1.z + a1.w) * 0.125f;
    }
    __syncthreads();

    int wf = tid & 63;
    int q  = tid >> 6;           // rank quarter 0..3
    int rb = q * 8;
    float acc1[8], acc2[8];
    #pragma unroll
    for (int u = 0; u < 8; u++) { acc1[u] = 0.f; acc2[u] = 0.f; }

    for (int c = 0; c < 64; c++) {
        float pv = P[c * 64 + wf];
        const float* wr = &WmT[c * 68];
        float4 w1a = *(const float4*)&wr[rb];
        float4 w1b = *(const float4*)&wr[rb + 4];
        float4 w2a = *(const float4*)&wr[32 + rb];
        float4 w2b = *(const float4*)&wr[32 + rb + 4];
        acc1[0] += w1a.x * pv; acc1[1] += w1a.y * pv;
        acc1[2] += w1a.z * pv; acc1[3] += w1a.w * pv;
        acc1[4] += w1b.x * pv; acc1[5] += w1b.y * pv;
        acc1[6] += w1b.z * pv; acc1[7] += w1b.w * pv;
        acc2[0] += w2a.x * pv; acc2[1] += w2a.y * pv;
        acc2[2] += w2a.z * pv; acc2[3] += w2a.w * pv;
        acc2[4] += w2b.x * pv; acc2[5] += w2b.y * pv;
        acc2[6] += w2b.z * pv; acc2[7] += w2b.w * pv;
    }

    float dtb = dt[b];
    float fre = 0.f, fim = 0.f;
    const float PIF = 3.14159265358979323846f;
    #pragma unroll
    for (int u = 0; u < 8; u++) {
        int r = rb + u;
        float p1 = acc1[u] + bs[r];
        float p2 = acc2[u] + bs[r + 32];
        float e   = __expf(p1);
        float dcy = exp2f(-dtb * __log2f(1.f + e));      // (1+e^p1)^(-dt)
        float e2  = __expf(2.f * p2);
        float th  = __fdividef(e2 - 1.f, e2 + 1.f) * PIF;
        float sa, ca;
        __sincosf(th * dtb, &sa, &ca);
        fre += dcy * ca;
        fim += dcy * sa;
    }
    redr[q * 64 + wf] = fre;
    redi[q * 64 + wf] = fim;
    __syncthreads();
    if (q == 0) {
        fre = redr[wf] + redr[64 + wf] + redr[128 + wf] + redr[192 + wf];
        fim = redi[wf] + redi[64 + wf] + redi[128 + wf] + redi[192 + wf];
        g_filtm1[(b * 64 + wf) * 256 + h] = make_float2(fre - 1.0f, fim);
    }
}

// ---------------- fused forward FFT256 + filter + inverse FFT256 ---------------
// A = S row (swizzled element order), B = per-warp scratch (256 float2).
__device__ __forceinline__ void fft256_roundtrip(float2* __restrict__ A,
                                                 float2* __restrict__ B,
                                                 const float2* __restrict__ TW,
                                                 int lane,
                                                 const float2* __restrict__ fg) {
    // ---- FWD stage 0: A(sw) -> B
    #pragma unroll
    for (int t2 = 0; t2 < 2; t2++) {
        int p  = lane + 32 * t2;
        int sp = sw(p);
        float2 a = A[sp], b = A[sp + 64], c = A[sp + 128], d = A[sp + 192];
        float2 w1 = TW[p << 1];
        float2 w2 = cmulf2(w1, w1);
        float2 w3 = cmulf2(w2, w1);
        float2 apc = cadd(a, c), amc = csub(a, c);
        float2 bpd = cadd(b, d), bmd = csub(b, d);
        float2 y0 = cadd(apc, bpd);
        float2 y2 = cmulf2(w2, csub(apc, bpd));
        float2 y1 = cmulf2(w1, make_float2(amc.x + bmd.y, amc.y - bmd.x));
        float2 y3 = cmulf2(w3, make_float2(amc.x - bmd.y, amc.y + bmd.x));
        float4* dst4 = (float4*)(B + 4 * p);
        dst4[0] = make_float4(y0.x, y0.y, y1.x, y1.y);
        dst4[1] = make_float4(y2.x, y2.y, y3.x, y3.y);
    }
    __syncwarp();
    // ---- FWD stage 1: B -> A(sw)
    #pragma unroll
    for (int t2 = 0; t2 < 2; t2++) {
        int t = lane + 32 * t2;
        int p = t >> 2, q = t & 3;
        float2 a = B[t], b = B[t + 64], c = B[t + 128], d = B[t + 192];
        float2 w1 = TW[p << 3];
        float2 w2 = cmulf2(w1, w1);
        float2 w3 = cmulf2(w2, w1);
        float2 apc = cadd(a, c), amc = csub(a, c);
        float2 bpd = cadd(b, d), bmd = csub(b, d);
        int base = q + 16 * p;
        int xb   = (p & 3) << 2;
        A[(base)      ^ xb] = cadd(apc, bpd);
        A[(base + 4)  ^ xb] = cmulf2(w1, make_float2(amc.x + bmd.y, amc.y - bmd.x));
        A[(base + 8)  ^ xb] = cmulf2(w2, csub(apc, bpd));
        A[(base + 12) ^ xb] = cmulf2(w3, make_float2(amc.x - bmd.y, amc.y + bmd.x));
    }
    __syncwarp();
    // ---- FWD stage 2: A(sw) -> B
    #pragma unroll
    for (int t2 = 0; t2 < 2; t2++) {
        int t  = lane + 32 * t2;
        int st = sw(t);
        int p = t >> 4, q = t & 15;
        float2 a = A[st], b = A[st + 64], c = A[st + 128], d = A[st + 192];
        float2 w1 = TW[p << 5];
        float2 w2 = cmulf2(w1, w1);
        float2 w3 = cmulf2(w2, w1);
        float2 apc = cadd(a, c), amc = csub(a, c);
        float2 bpd = cadd(b, d), bmd = csub(b, d);
        int base = q + 64 * p;
        B[base]      = cadd(apc, bpd);
        B[base + 16] = cmulf2(w1, make_float2(amc.x + bmd.y, amc.y - bmd.x));
        B[base + 32] = cmulf2(w2, csub(apc, bpd));
        B[base + 48] = cmulf2(w3, make_float2(amc.x - bmd.y, amc.y + bmd.x));
    }
    __syncwarp();
    // ---- FUSED: FWD stage 3 + filter + INV stage 0, all in registers: B -> B
    {
        float2 rr[8];
        #pragma unroll
        for (int t2 = 0; t2 < 2; t2++) {
            int q = lane + 32 * t2;
            rr[4*t2+0] = B[q];       rr[4*t2+1] = B[q + 64];
            rr[4*t2+2] = B[q + 128]; rr[4*t2+3] = B[q + 192];
        }
        #pragma unroll
        for (int t2 = 0; t2 < 2; t2++) {
            int q = lane + 32 * t2;
            float2 f0 = __ldg(&fg[q]),       f1 = __ldg(&fg[q + 64]);
            float2 f2 = __ldg(&fg[q + 128]), f3 = __ldg(&fg[q + 192]);
            float2 a = rr[4*t2+0], b = rr[4*t2+1], c = rr[4*t2+2], d = rr[4*t2+3];
            float2 apc = cadd(a, c), amc = csub(a, c);
            float2 bpd = cadd(b, d), bmd = csub(b, d);
            float2 y0 = cadd(apc, bpd);
            float2 y1 = make_float2(amc.x + bmd.y, amc.y - bmd.x);
            float2 y2 = csub(apc, bpd);
            float2 y3 = make_float2(amc.x - bmd.y, amc.y + bmd.x);
            y0 = cmulf2(y0, f0); y1 = cmulf2(y1, f1);
            y2 = cmulf2(y2, f2); y3 = cmulf2(y3, f3);
            float2 w1 = TW[q << 1]; w1.y = -w1.y;
            float2 w2 = cmulf2(w1, w1);
            float2 w3 = cmulf2(w2, w1);
            apc = cadd(y0, y2); amc = csub(y0, y2);
            bpd = cadd(y1, y3); bmd = csub(y1, y3);
            float2 z0 = cadd(apc, bpd);
            float2 z2 = cmulf2(w2, csub(apc, bpd));
            float2 z1 = cmulf2(w1, make_float2(amc.x - bmd.y, amc.y + bmd.x));
            float2 z3 = cmulf2(w3, make_float2(amc.x + bmd.y, amc.y - bmd.x));
            float4* dst4 = (float4*)(B + 4 * q);
            dst4[0] = make_float4(z0.x, z0.y, z1.x, z1.y);
            dst4[1] = make_float4(z2.x, z2.y, z3.x, z3.y);
        }
    }
    __syncwarp();
    // ---- INV stage 1: B -> A(sw)
    #pragma unroll
    for (int t2 = 0; t2 < 2; t2++) {
        int t = lane + 32 * t2;
        int p = t >> 2, q = t & 3;
        float2 a = B[t], b = B[t + 64], c = B[t + 128], d = B[t + 192];
        float2 w1 = TW[p << 3]; w1.y = -w1.y;
        float2 w2 = cmulf2(w1, w1);
        float2 w3 = cmulf2(w2, w1);
        float2 apc = cadd(a, c), amc = csub(a, c);
        float2 bpd = cadd(b, d), bmd = csub(b, d);
        int base = q + 16 * p;
        int xb   = (p & 3) << 2;
        A[(base)      ^ xb] = cadd(apc, bpd);
        A[(base + 4)  ^ xb] = cmulf2(w1, make_float2(amc.x - bmd.y, amc.y + bmd.x));
        A[(base + 8)  ^ xb] = cmulf2(w2, csub(apc, bpd));
        A[(base + 12) ^ xb] = cmulf2(w3, make_float2(amc.x + bmd.y, amc.y - bmd.x));
    }
    __syncwarp();
    // ---- INV stage 2: A(sw) -> B
    #pragma unroll
    for (int t2 = 0; t2 < 2; t2++) {
        int t  = lane + 32 * t2;
        int st = sw(t);
        int p = t >> 4, q = t & 15;
        float2 a = A[st], b = A[st + 64], c = A[st + 128], d = A[st + 192];
        float2 w1 = TW[p << 5]; w1.y = -w1.y;
        float2 w2 = cmulf2(w1, w1);
        float2 w3 = cmulf2(w2, w1);
        float2 apc = cadd(a, c), amc = csub(a, c);
        float2 bpd = cadd(b, d), bmd = csub(b, d);
        int base = q + 64 * p;
        B[base]      = cadd(apc, bpd);
        B[base + 16] = cmulf2(w1, make_float2(amc.x - bmd.y, amc.y + bmd.x));
        B[base + 32] = cmulf2(w2, csub(apc, bpd));
        B[base + 48] = cmulf2(w3, make_float2(amc.x + bmd.y, amc.y - bmd.x));
    }
    __syncwarp();
    // ---- INV stage 3: B -> A(sw), no twiddle
    #pragma unroll
    for (int t2 = 0; t2 < 2; t2++) {
        int q  = lane + 32 * t2;
        int sq = sw(q);
        float2 a = B[q], b = B[q + 64], c = B[q + 128], d = B[q + 192];
        float2 apc = cadd(a, c), amc = csub(a, c);
        float2 bpd = cadd(b, d), bmd = csub(b, d);
        A[sq]       = cadd(apc, bpd);
        A[sq + 64]  = make_float2(amc.x - bmd.y, amc.y + bmd.x);
        A[sq + 128] = csub(apc, bpd);
        A[sq + 192] = make_float2(amc.x + bmd.y, amc.y - bmd.x);
    }
    __syncwarp();
}

// ---------------- fused main kernel: 1024 threads, 16 row-groups ----------------
#define S_STRIDE 257
#define G_STRIDE 68
#define GRP_PER  (8 * G_STRIDE)                   // 544 float2 per 64-thread group
#define NGRP 16
#define SMEM_BYTES ((64 * S_STRIDE + 512 + NGRP * GRP_PER) * 8)

#define BARG() asm volatile("bar.sync %0, %1;" :: "r"(bar_id), "r"(bar_cnt) : "memory")

__global__ void __launch_bounds__(1024, 1)
k_main(const float* __restrict__ x, float* __restrict__ out) {
    extern __shared__ char smem_raw[];
    float2* S   = (float2*)smem_raw;            // [64][257] tile X[k][sw(h)]
    float2* TW  = S + 64 * S_STRIDE;            // 512 twiddles
    float2* GRP = TW + 512;                     // 16 groups x 544

    int tid  = threadIdx.x;
    int bc   = blockIdx.x;
    int b    = bc >> 6;
    const float* xim = x   + (size_t)bc * (HH * WW);
    float*       oim = out + (size_t)bc * (HH * WW);

    if (tid < 512) {
        float s, c;
        sincospif((float)tid / 256.0f, &s, &c);
        TW[tid] = make_float2(c, -s);
    }
    __syncthreads();

    int pair = tid >> 6;        // 0..15 group id
    int t64  = tid & 63;
    int bar_id  = (pair < 15) ? (pair + 1) : 15;
    int bar_cnt = (pair >= 14) ? 128 : 64;
    float2* grp = GRP + pair * GRP_PER;
    int m8  = t64 >> 3;
    int j08 = t64 & 7;
    int rowm = (m8 == 0 || m8 == 4) ? 0 : ((m8 < 4) ? m8 : 8 - m8);

    // ================= Phase A: partial forward W-DFT (512 -> 64 bins) ========
    float v[8];
    {
        const float* row0 = xim + pair * 512;
        #pragma unroll
        for (int u = 0; u < 8; u++) v[u] = row0[t64 + 64 * u];
    }
    for (int it = 0; it < 16; it++) {
        int h  = it * 16 + pair;
        int hs = sw(h);
        // ---- step1: real DFT8, symmetric half only (G0,G4 packed; G1..G3)
        {
            int j = t64;
            float e0 = v[0] + v[4], e1 = v[1] + v[5], e2 = v[2] + v[6], e3 = v[3] + v[7];
            float o0 = v[0] - v[4], o1 = v[1] - v[5], o2 = v[2] - v[6], o3 = v[3] - v[7];
            float s02 = e0 + e2, s13 = e1 + e3, d02 = e0 - e2, d13 = e1 - e3;
            const float R = 0.70710678118654752f;
            float t1 = R * (o1 - o3), t2 = R * (o1 + o3);
            grp[0 * G_STRIDE + j] = make_float2(s02 + s13, s02 - s13);  // G0 | G4
            grp[1 * G_STRIDE + j] = make_float2(o0 + t1, -o2 - t2);     // G1
            grp[2 * G_STRIDE + j] = make_float2(d02, -d13);             // G2
            grp[3 * G_STRIDE + j] = make_float2(o0 - t1,  o2 - t2);     // G3
        }
        BARG();
        // prefetch next row
        if (it < 15) {
            const float* nr = xim + (h + 16) * 512;
            #pragma unroll
            for (int u = 0; u < 8; u++) v[u] = nr[t64 + 64 * u];
        }
        // ---- pass1: P[m][t][j0] = DFT8_{j1}( W64^{m j1} G[m][j0+8j1] )
        {
            float2 wm = TW[8 * m8];
            float2 w  = make_float2(1.f, 0.f);
            float2 z[8];
            #pragma unroll
            for (int j1 = 0; j1 < 8; j1++) {
                float2 raw = grp[rowm * G_STRIDE + j08 + 8 * j1];
                float2 g;
                if (m8 == 0)      g = make_float2(raw.x, 0.f);
                else if (m8 == 4) g = make_float2(raw.y, 0.f);
                else if (m8 < 4)  g = raw;
                else              g = make_float2(raw.x, -raw.y);
                z[j1] = cmulf2(g, w);
                w = cmulf2(w, wm);
            }
            dft8<1>(z);
            BARG();   // all G reads complete before P overwrites shared rows
            #pragma unroll
            for (int t = 0; t < 8; t++)
                grp[m8 * G_STRIDE + t * 8 + j08] = z[t];
        }
        BARG();
        // ---- pass2: X[k] = sum_{j0} W512^{k j0} P[k&7][k>>3][j0]
        {
            int k = t64, mm = k & 7, tt = k >> 3;
            const float4* pp = (const float4*)(grp + mm * G_STRIDE + tt * 8);
            float2 wk = TW[k];
            float2 w  = make_float2(1.f, 0.f);
            float2 acc = make_float2(0.f, 0.f);
            #pragma unroll
            for (int q = 0; q < 4; q++) {
                float4 g2 = pp[q];
                acc.x += w.x * g2.x - w.y * g2.y;
                acc.y += w.x * g2.y + w.y * g2.x;
                w = cmulf2(w, wk);
                acc.x += w.x * g2.z - w.y * g2.w;
                acc.y += w.x * g2.w + w.y * g2.z;
                w = cmulf2(w, wk);
            }
            S[k * S_STRIDE + hs] = acc;
        }
        BARG();
    }
    __syncthreads();

    // ================= Phase B: fused FFT / filter / IFFT along H =============
    {
        int wid  = tid >> 5;                // 0..31
        int lane = tid & 31;
        float2* scr = GRP + wid * 272;      // 32 warps x 272 = 8704 = 16*544
        for (int k = wid; k < 64; k += 32) {
            float2* row = S + k * S_STRIDE;
            const float2* fg = &g_filtm1[(b * 64 + k) * 256];
            fft256_roundtrip(row, scr, TW, lane, fg);
        }
    }
    __syncthreads();

    // ================= Phase C: partial inverse W-DFT, out = x + delta ========
    const float SCALE = 2.0f / (256.0f * 512.0f);
    for (int it = 0; it < 16; it++) {
        int h  = it * 16 + pair;
        int hs = sw(h);
        const float* rowx = xim + h * 512;
        float xv[8];
        #pragma unroll
        for (int u = 0; u < 8; u++) xv[u] = rowx[t64 + 64 * u];
        // ---- pass1: R = IDFT8_a( conj(W64^{a j0}) Z[8a+m] ); Q = conj(W512^{m j}) R
        {
            float2 ws = TW[8 * j08];
            float2 w  = make_float2(1.f, 0.f);
            float2 z[8];
            #pragma unroll
            for (int a = 0; a < 8; a++) {
                float2 zz = S[(8 * a + m8) * S_STRIDE + hs];
                z[a] = cmulcf2(zz, w);
                w = cmulf2(w, ws);
            }
            if (m8 == 0) { z[0].x *= 0.5f; z[0].y *= 0.5f; }
            dft8<-1>(z);
            float2 wq  = TW[(m8 * j08) & 511];
            float2 wqs = TW[8 * m8];
            #pragma unroll
            for (int j1 = 0; j1 < 8; j1++) {
                grp[m8 * G_STRIDE + j08 + 8 * j1] = cmulcf2(z[j1], wq);
                wq = cmulf2(wq, wqs);
            }
        }
        BARG();
        // ---- output: delta[j+64u] = Re( IDFT8_m(Q)[u] )
        {
            int j = t64;
            float2 Q[8];
            #pragma unroll
            for (int mm = 0; mm < 8; mm++) Q[mm] = grp[mm * G_STRIDE + j];
            dft8<-1>(Q);          // Q[u] = sum_m e^{+2pi i m u/8} Q_m
            float* orow = oim + h * 512;
            #pragma unroll
            for (int u = 0; u < 8; u++)
                orow[j + 64 * u] = xv[u] + Q[u].x * SCALE;
        }
        BARG();
    }
}

// ---------------- launcher ------------------------------------------------------
extern "C" void kernel_launch(void* const* d_in, const int* in_sizes, int n_in,
                              void* d_out, int out_size) {
    const float* x = nullptr; const float* dt = nullptr;
    const float* cw = nullptr; const float* cb = nullptr;
    for (int i = 0; i < n_in; i++) {
        int s = in_sizes[i];
        if      (s == BATCH * CH * HH * WW) x  = (const float*)d_in[i];
        else if (s == BATCH)                dt = (const float*)d_in[i];
        else if (s == 64 * 64)              cw = (const float*)d_in[i];
        else if (s == 64)                   cb = (const float*)d_in[i];
    }
    float* out = (float*)d_out;

    cudaFuncSetAttribute(k_main, cudaFuncAttributeMaxDynamicSharedMemorySize,
                         SMEM_BYTES);

    k_filt<<<BATCH * 256, 256>>>(x, cw, cb, dt);
    k_main<<<BATCH * CH, 1024, SMEM_BYTES>>>(x, out);
}